// round 2
// baseline (speedup 1.0000x reference)
#include <cuda_runtime.h>
#include <cstdint>

// ---------------------------------------------------------------------------
// SparseMotionEncoder on GB300 — round 1: fp32 SIMT register-tiled gather-GEMMs
//
// Pipeline:
//   corr1 = relu(corr_features @ Wc1 + bc1)                  [N,324]->[N,256]
//   cat[:, 0:192]   = relu(subm_conv(corr1, nbr3, Wc2))      K=27, 256->192
//   f1    = relu(subm_conv(flow,  nbr7, Wf1))                K=343,  2->128
//   cat[:,192:256]  = relu(subm_conv(f1,   nbr3, Wf2))       K=27, 128-> 64
//   out[:,0:120]    = relu(subm_conv(cat,  nbr3, Wcat))      K=27, 256->120
//   out[:,120:122]  = flow ; out[:,122:128] = extrinsics
// ---------------------------------------------------------------------------

#define NVOX_MAX 50000

__device__ float g_corr1[NVOX_MAX * 256];   // output of pointwise conv
__device__ float g_f1[NVOX_MAX * 128];      // output of flow conv (K=343)
__device__ float g_cat[NVOX_MAX * 256];     // fused concat buffer [corr2 | f2]

// ---------------------------------------------------------------------------
// Generic submanifold-conv GEMM:
//   out[n, ocol + c] = relu( sum_k sum_ci gather(feat, nbr[k][n])[ci] * W[k][ci][c] + b[c] )
// Block tile: 128 rows x 64 cols, BK=16, 256 threads, 8x4 per-thread microtile.
// nbr == nullptr means identity (pointwise, KK must be 1).
// ---------------------------------------------------------------------------
template <int KK, int CIN, int COUT, bool RELU>
__global__ void __launch_bounds__(256)
subm_gemm(const float* __restrict__ feat, int fstride,
          const int* __restrict__ nbr,
          const float* __restrict__ W,
          const float* __restrict__ bias,
          float* __restrict__ out, int ostride, int ocol,
          int N)
{
    constexpr int BM = 128, BN = 64, BK = 16;

    __shared__ int   sIdx[KK][BM];
    __shared__ float As[BK][BM + 4];   // transposed A tile (pad vs conflicts)
    __shared__ float Bs[BK][BN];

    const int t    = threadIdx.x;          // 0..255
    const int row0 = blockIdx.x * BM;
    const int col0 = blockIdx.y * BN;
    const int ty   = t >> 4;               // 0..15 -> rows ty*8 .. ty*8+7
    const int tx   = t & 15;               // 0..15 -> cols tx*4 .. tx*4+3

    // Load all K neighbor indices for this row tile once.
    for (int e = t; e < KK * BM; e += 256) {
        int k = e / BM, m = e % BM;
        int r = row0 + m;
        int idx = -1;
        if (r < N) idx = nbr ? nbr[(size_t)k * N + r] : r;
        sIdx[k][m] = idx;
    }

    float acc[8][4];
#pragma unroll
    for (int i = 0; i < 8; ++i)
#pragma unroll
        for (int j = 0; j < 4; ++j) acc[i][j] = 0.f;

    __syncthreads();

    for (int k = 0; k < KK; ++k) {
        const float* __restrict__ Wk = W + (size_t)k * CIN * COUT;

        for (int c0 = 0; c0 < CIN; c0 += BK) {
            // --- load gathered A tile: 128 rows x 16 cols, 8 elems/thread ---
            {
                const int c = t & 15;
                const int mrow = t >> 4;
                const bool cin_ok = (c0 + c) < CIN;
#pragma unroll
                for (int p = 0; p < 8; ++p) {
                    int m = p * 16 + mrow;
                    int idx = sIdx[k][m];
                    float v = 0.f;
                    if (idx >= 0 && cin_ok)
                        v = feat[(size_t)idx * fstride + c0 + c];
                    As[c][m] = v;
                }
            }
            // --- load B tile: 16 rows x 64 cols, float4/thread ---
            {
                int r  = t >> 4;            // 0..15
                int c4 = (t & 15) * 4;      // 0..60
                float4 v = make_float4(0.f, 0.f, 0.f, 0.f);
                if (c0 + r < CIN) {
                    int gc = col0 + c4;
                    if (gc + 3 < COUT) {
                        v = *reinterpret_cast<const float4*>(
                                &Wk[(size_t)(c0 + r) * COUT + gc]);
                    } else {
                        float tmp[4] = {0.f, 0.f, 0.f, 0.f};
#pragma unroll
                        for (int j = 0; j < 4; ++j)
                            if (gc + j < COUT)
                                tmp[j] = Wk[(size_t)(c0 + r) * COUT + gc + j];
                        v = make_float4(tmp[0], tmp[1], tmp[2], tmp[3]);
                    }
                }
                *reinterpret_cast<float4*>(&Bs[r][c4]) = v;
            }
            __syncthreads();

#pragma unroll
            for (int kk = 0; kk < BK; ++kk) {
                float a[8], bb[4];
#pragma unroll
                for (int i = 0; i < 8; ++i) a[i] = As[kk][ty * 8 + i];
#pragma unroll
                for (int j = 0; j < 4; ++j) bb[j] = Bs[kk][tx * 4 + j];
#pragma unroll
                for (int i = 0; i < 8; ++i)
#pragma unroll
                    for (int j = 0; j < 4; ++j)
                        acc[i][j] = fmaf(a[i], bb[j], acc[i][j]);
            }
            __syncthreads();
        }
    }

    // --- epilogue: bias + relu + store ---
#pragma unroll
    for (int i = 0; i < 8; ++i) {
        int r = row0 + ty * 8 + i;
        if (r >= N) continue;
#pragma unroll
        for (int j = 0; j < 4; ++j) {
            int c = col0 + tx * 4 + j;
            if (c >= COUT) continue;
            float v = acc[i][j] + bias[c];
            if (RELU) v = fmaxf(v, 0.f);
            out[(size_t)r * ostride + ocol + c] = v;
        }
    }
}

// ---------------------------------------------------------------------------
// Flow conv: K=343, Cin=2, Cout=128. Tiny Cin -> custom kernel, double-buffered
// smem for gathered flow pairs and per-offset weights. 64 rows x 128 cols tile.
// ---------------------------------------------------------------------------
__global__ void __launch_bounds__(256)
flow_conv(const float* __restrict__ flow, const int* __restrict__ nbr7,
          const float* __restrict__ W, const float* __restrict__ bias,
          float* __restrict__ out, int N)
{
    constexpr int KK = 343, BM = 64;
    __shared__ float sF[2][BM * 2];
    __shared__ float sW[2][256];

    const int t    = threadIdx.x;
    const int row0 = blockIdx.x * BM;
    const int ty   = t >> 5;    // 0..7  -> rows ty*8..ty*8+7
    const int tx   = t & 31;    // 0..31 -> cols tx*4..tx*4+3

    float acc[8][4];
#pragma unroll
    for (int i = 0; i < 8; ++i)
#pragma unroll
        for (int j = 0; j < 4; ++j) acc[i][j] = 0.f;

    auto load_stage = [&](int k, int buf) {
        if (t < BM) {
            int r = row0 + t;
            int idx = (r < N) ? nbr7[(size_t)k * N + r] : -1;
            float2 v = make_float2(0.f, 0.f);
            if (idx >= 0)
                v = *reinterpret_cast<const float2*>(&flow[(size_t)idx * 2]);
            sF[buf][t * 2]     = v.x;
            sF[buf][t * 2 + 1] = v.y;
        }
        sW[buf][t] = W[(size_t)k * 256 + t];
    };

    load_stage(0, 0);

    for (int k = 0; k < KK; ++k) {
        __syncthreads();
        if (k + 1 < KK) load_stage(k + 1, (k + 1) & 1);
        const int buf = k & 1;

        float w0[4], w1[4];
#pragma unroll
        for (int j = 0; j < 4; ++j) {
            w0[j] = sW[buf][tx * 4 + j];
            w1[j] = sW[buf][128 + tx * 4 + j];
        }
#pragma unroll
        for (int i = 0; i < 8; ++i) {
            float f0 = sF[buf][(ty * 8 + i) * 2];
            float f1 = sF[buf][(ty * 8 + i) * 2 + 1];
#pragma unroll
            for (int j = 0; j < 4; ++j)
                acc[i][j] = fmaf(f0, w0[j], fmaf(f1, w1[j], acc[i][j]));
        }
    }

#pragma unroll
    for (int i = 0; i < 8; ++i) {
        int r = row0 + ty * 8 + i;
        if (r >= N) continue;
#pragma unroll
        for (int j = 0; j < 4; ++j) {
            int c = tx * 4 + j;
            float v = fmaxf(acc[i][j] + bias[c], 0.f);
            out[(size_t)r * 128 + c] = v;
        }
    }
}

// out[:,120:122] = flow, out[:,122:128] = extrinsics
__global__ void tail_copy(const float* __restrict__ ext,
                          const float* __restrict__ flow,
                          float* __restrict__ out, int N)
{
    int i = blockIdx.x * blockDim.x + threadIdx.x;
    if (i >= N * 8) return;
    int r = i >> 3, c = i & 7;
    float v = (c < 2) ? flow[(size_t)r * 2 + c] : ext[(size_t)r * 6 + (c - 2)];
    out[(size_t)r * 128 + 120 + c] = v;
}

extern "C" void kernel_launch(void* const* d_in, const int* in_sizes, int n_in,
                              void* d_out, int out_size)
{
    const float* extr  = (const float*)d_in[0];   // [N,6]
    const float* flow  = (const float*)d_in[1];   // [N,2]
    const float* corrf = (const float*)d_in[2];   // [N,324]
    const int*   nbr3  = (const int*)  d_in[3];   // [27,N]
    const int*   nbr7  = (const int*)  d_in[4];   // [343,N]
    const float* Wc1   = (const float*)d_in[5];   // [324,256]
    const float* bc1   = (const float*)d_in[6];
    const float* Wc2   = (const float*)d_in[7];   // [27,256,192]
    const float* bc2   = (const float*)d_in[8];
    const float* Wf1   = (const float*)d_in[9];   // [343,2,128]
    const float* bf1   = (const float*)d_in[10];
    const float* Wf2   = (const float*)d_in[11];  // [27,128,64]
    const float* bf2   = (const float*)d_in[12];
    const float* Wcat  = (const float*)d_in[13];  // [27,256,120]
    const float* bcat  = (const float*)d_in[14];
    float* out = (float*)d_out;

    const int N = in_sizes[0] / 6;  // 50000

    float *p_corr1, *p_f1, *p_cat;
    cudaGetSymbolAddress((void**)&p_corr1, g_corr1);
    cudaGetSymbolAddress((void**)&p_f1,    g_f1);
    cudaGetSymbolAddress((void**)&p_cat,   g_cat);

    const int mblk = (N + 127) / 128;

    // corr1 = relu(corrf @ Wc1 + bc1)
    subm_gemm<1, 324, 256, true><<<dim3(mblk, 4), 256>>>(
        corrf, 324, nullptr, Wc1, bc1, p_corr1, 256, 0, N);

    // f1 = relu(flow_conv)
    flow_conv<<<(N + 63) / 64, 256>>>(flow, nbr7, Wf1, bf1, p_f1, N);

    // cat[:,0:192] = relu(conv(corr1, nbr3, Wc2))
    subm_gemm<27, 256, 192, true><<<dim3(mblk, 3), 256>>>(
        p_corr1, 256, nbr3, Wc2, bc2, p_cat, 256, 0, N);

    // cat[:,192:256] = relu(conv(f1, nbr3, Wf2))
    subm_gemm<27, 128, 64, true><<<dim3(mblk, 1), 256>>>(
        p_f1, 128, nbr3, Wf2, bf2, p_cat, 256, 192, N);

    // out[:,0:120] = relu(conv(cat, nbr3, Wcat))
    subm_gemm<27, 256, 120, true><<<dim3(mblk, 2), 256>>>(
        p_cat, 256, nbr3, Wcat, bcat, out, 128, 0, N);

    // out[:,120:128] = [flow, extrinsics]
    tail_copy<<<(N * 8 + 255) / 256, 256>>>(extr, flow, out, N);
}

// round 4
// speedup vs baseline: 2.5487x; 2.5487x over previous
#include <cuda_runtime.h>
#include <cuda_bf16.h>
#include <cstdint>

// ===========================================================================
// SparseMotionEncoder — round 4: mma.sync (HMMA) bf16x3 split-precision
// gather-GEMMs. tcgen05 is unavailable (harness PTX targets compute_103
// family, not sm_103a), so we use the baseline m16n8k16 bf16 tensor path.
//
//   corr1 = relu(corrf @ Wc1 + bc1)                 tmma<1,324>   (identity)
//   cat[:,0:192]  = relu(conv(corr1,nbr3,Wc2))      tmma<27,256>
//   f1    = relu(conv(flow, nbr7, Wf1))             SIMT flow_conv
//   cat[:,192:256]= relu(conv(f1,  nbr3,Wf2))       tmma<27,128>
//   out[:,0:120]  = relu(conv(cat, nbr3,Wcat))      tmma<27,256>
//   out[:,120:128]= [flow, extrinsics]
//
// Numerics: x = hi + lo (bf16 each); D = Ah*Bh + Al*Bh + Ah*Bl, fp32 acc.
// ===========================================================================

#define NVOX 50000

__device__ float g_corr1[NVOX * 256];
__device__ float g_f1[NVOX * 128];
__device__ float g_cat[NVOX * 256];

// Transposed, split weights: [KK][COUTPAD][CINPAD] bf16, zero padded.
__device__ __nv_bfloat16 gW_c1_hi[1 * 256 * 352], gW_c1_lo[1 * 256 * 352];
__device__ __nv_bfloat16 gW_c2_hi[27 * 192 * 256], gW_c2_lo[27 * 192 * 256];
__device__ __nv_bfloat16 gW_f2_hi[27 * 64 * 128],  gW_f2_lo[27 * 64 * 128];
__device__ __nv_bfloat16 gW_ct_hi[27 * 128 * 256], gW_ct_lo[27 * 128 * 256];

__device__ __forceinline__ uint32_t pkbf(float a, float b) {
    __nv_bfloat162 t = __floats2bfloat162_rn(a, b);
    return *reinterpret_cast<uint32_t*>(&t);
}

__device__ __forceinline__ void mma16816(float* c, const uint32_t* a,
                                         const uint32_t* b) {
    asm volatile(
        "mma.sync.aligned.m16n8k16.row.col.f32.bf16.bf16.f32 "
        "{%0,%1,%2,%3}, {%4,%5,%6,%7}, {%8,%9}, {%0,%1,%2,%3};"
        : "+f"(c[0]), "+f"(c[1]), "+f"(c[2]), "+f"(c[3])
        : "r"(a[0]), "r"(a[1]), "r"(a[2]), "r"(a[3]), "r"(b[0]), "r"(b[1]));
}

// ---------------------------------------------------------------------------
// Weight prep: W[k][c][n] fp32 -> Wt_hi/lo[k][n][c] bf16, zero padded.
// ---------------------------------------------------------------------------
template <int KK, int CIN, int COUT, int CINPAD, int COUTPAD>
__global__ void prep_w(const float* __restrict__ W,
                       __nv_bfloat16* __restrict__ hi,
                       __nv_bfloat16* __restrict__ lo)
{
    long tid = (long)blockIdx.x * blockDim.x + threadIdx.x;
    const long total = (long)KK * COUTPAD * CINPAD;
    if (tid >= total) return;
    int c = tid % CINPAD;
    long r = tid / CINPAD;
    int n = r % COUTPAD;
    int k = r / COUTPAD;
    float x = (c < CIN && n < COUT) ? W[((size_t)k * CIN + c) * COUT + n] : 0.f;
    __nv_bfloat16 h = __float2bfloat16(x);
    hi[tid] = h;
    lo[tid] = __float2bfloat16(x - __bfloat162float(h));
}

// ---------------------------------------------------------------------------
// HMMA gather-GEMM. CTA tile 128(M) x 64(N), BK=32, 256 threads = 8 warps in
// 4x2 grid, warp tile 32x32. A gathered fp32 -> split bf16 hi/lo in smem;
// B copied from pre-split transposed weights. 3 mma products per tile.
// smem rows padded to 40 halves (20 b32) -> conflict-free fragment reads.
// ---------------------------------------------------------------------------
template <int KK, int CIN, int CINPAD, int COUTPAD>
__global__ void __launch_bounds__(256)
tmma(const float* __restrict__ feat, int fstride, const int* __restrict__ nbr,
     const __nv_bfloat16* __restrict__ Whi, const __nv_bfloat16* __restrict__ Wlo,
     const float* __restrict__ bias, float* __restrict__ out,
     int ostride, int ocol, int COUT, int N)
{
    constexpr bool TAIL = (CIN % 32) != 0;
    constexpr int CH = CINPAD / 32;
    constexpr int RS = 20;          // row stride in b32 (40 halves)

    __shared__ int sIdx[KK][128];
    extern __shared__ char dyn[];
    // dyn layout: Ah[128*40h]=10240B, Al=10240B, Bh[64*40h]=5120B, Bl=5120B
    uint32_t* bAh = (uint32_t*)(dyn);
    uint32_t* bAl = (uint32_t*)(dyn + 10240);
    uint32_t* bBh = (uint32_t*)(dyn + 20480);
    uint32_t* bBl = (uint32_t*)(dyn + 25600);

    const int t = threadIdx.x, lane = t & 31, w = t >> 5;
    const int wm = w >> 1, wn = w & 1;
    const int g = lane >> 2, tg = lane & 3;
    const int row0 = blockIdx.x * 128;
    const int n0 = blockIdx.y * 64;

    for (int e = t; e < KK * 128; e += 256) {
        int k = e >> 7, m = e & 127;
        int r = row0 + m;
        sIdx[k][m] = (r < N) ? (nbr ? nbr[(size_t)k * N + r] : r) : -1;
    }

    float acc[2][4][4];
#pragma unroll
    for (int i = 0; i < 2; ++i)
#pragma unroll
        for (int j = 0; j < 4; ++j)
#pragma unroll
            for (int q = 0; q < 4; ++q) acc[i][j][q] = 0.f;

    __syncthreads();

    const int gr = t >> 1;           // gather row 0..127
    const int gc = (t & 1) * 16;     // col base within 32-chunk
    const int bn = t >> 2;           // B row 0..63
    const int bc = (t & 3) * 8;      // B col base (halves)

    for (int k = 0; k < KK; ++k) {
        const int idx = sIdx[k][gr];
        const float* frow = (idx >= 0) ? feat + (size_t)idx * fstride : nullptr;
        const size_t wrow = ((size_t)k * COUTPAD + n0 + bn) * CINPAD + bc;

        for (int cc = 0; cc < CH; ++cc) {
            const int c0 = cc * 32;
            __syncthreads();   // previous compute done before overwrite

            // ---- A gather + split -> smem ----
#pragma unroll
            for (int i = 0; i < 4; ++i) {
                const int c = gc + i * 4;
                const int gcol = c0 + c;
                float4 v = make_float4(0.f, 0.f, 0.f, 0.f);
                if (frow) {
                    if (!TAIL || gcol + 3 < CIN) {
                        v = *reinterpret_cast<const float4*>(frow + gcol);
                    } else {
                        float tmp[4] = {0.f, 0.f, 0.f, 0.f};
#pragma unroll
                        for (int jj = 0; jj < 4; ++jj)
                            if (gcol + jj < CIN) tmp[jj] = frow[gcol + jj];
                        v = make_float4(tmp[0], tmp[1], tmp[2], tmp[3]);
                    }
                }
                float hx = __bfloat162float(__float2bfloat16(v.x));
                float hy = __bfloat162float(__float2bfloat16(v.y));
                float hz = __bfloat162float(__float2bfloat16(v.z));
                float hw = __bfloat162float(__float2bfloat16(v.w));
                uint2 uh = make_uint2(pkbf(hx, hy), pkbf(hz, hw));
                uint2 ul = make_uint2(pkbf(v.x - hx, v.y - hy),
                                      pkbf(v.z - hz, v.w - hw));
                const int b32off = gr * RS + (c >> 1);   // c even
                *reinterpret_cast<uint2*>(bAh + b32off) = uh;
                *reinterpret_cast<uint2*>(bAl + b32off) = ul;
            }

            // ---- B copy (pre-split transposed weights) ----
            {
                const uint4 vh = *reinterpret_cast<const uint4*>(Whi + wrow + c0);
                const uint4 vl = *reinterpret_cast<const uint4*>(Wlo + wrow + c0);
                const int b32off = bn * RS + (bc >> 1);
                *reinterpret_cast<uint4*>(bBh + b32off) = vh;
                *reinterpret_cast<uint4*>(bBl + b32off) = vl;
            }
            __syncthreads();

            // ---- compute: 2 k16 steps, 2 mtiles x 4 ntiles x 3 products ----
#pragma unroll
            for (int ks = 0; ks < 2; ++ks) {
                uint32_t Ah[2][4], Al[2][4];
#pragma unroll
                for (int i = 0; i < 2; ++i) {
                    const int ab = (wm * 32 + i * 16 + g) * RS + ks * 8 + tg;
                    Ah[i][0] = bAh[ab];
                    Ah[i][1] = bAh[ab + 8 * RS];
                    Ah[i][2] = bAh[ab + 4];
                    Ah[i][3] = bAh[ab + 8 * RS + 4];
                    Al[i][0] = bAl[ab];
                    Al[i][1] = bAl[ab + 8 * RS];
                    Al[i][2] = bAl[ab + 4];
                    Al[i][3] = bAl[ab + 8 * RS + 4];
                }
#pragma unroll
                for (int j = 0; j < 4; ++j) {
                    const int nb = (wn * 32 + j * 8 + g) * RS + ks * 8 + tg;
                    uint32_t Bh[2] = {bBh[nb], bBh[nb + 4]};
                    uint32_t Bl[2] = {bBl[nb], bBl[nb + 4]};
#pragma unroll
                    for (int i = 0; i < 2; ++i) {
                        mma16816(acc[i][j], Ah[i], Bh);
                        mma16816(acc[i][j], Al[i], Bh);
                        mma16816(acc[i][j], Ah[i], Bl);
                    }
                }
            }
        }
    }

    // ---- epilogue: bias + relu -> global ----
#pragma unroll
    for (int j = 0; j < 4; ++j) {
        const int col = n0 + wn * 32 + j * 8 + tg * 2;
        if (col >= COUT) continue;
        const float2 bv = *reinterpret_cast<const float2*>(bias + col);
#pragma unroll
        for (int i = 0; i < 2; ++i) {
            const int r1 = row0 + wm * 32 + i * 16 + g;
            if (r1 < N) {
                float2 o = make_float2(fmaxf(acc[i][j][0] + bv.x, 0.f),
                                       fmaxf(acc[i][j][1] + bv.y, 0.f));
                *reinterpret_cast<float2*>(out + (size_t)r1 * ostride + ocol + col) = o;
            }
            const int r2 = r1 + 8;
            if (r2 < N) {
                float2 o = make_float2(fmaxf(acc[i][j][2] + bv.x, 0.f),
                                       fmaxf(acc[i][j][3] + bv.y, 0.f));
                *reinterpret_cast<float2*>(out + (size_t)r2 * ostride + ocol + col) = o;
            }
        }
    }
}

// ---------------------------------------------------------------------------
// Flow conv (K=343, Cin=2, Cout=128): SIMT, double-buffered.
// ---------------------------------------------------------------------------
__global__ void __launch_bounds__(256)
flow_conv(const float* __restrict__ flow, const int* __restrict__ nbr7,
          const float* __restrict__ W, const float* __restrict__ bias,
          float* __restrict__ out, int N)
{
    constexpr int KK = 343, BM = 64;
    __shared__ float sF[2][BM * 2];
    __shared__ float sW[2][256];

    const int t = threadIdx.x;
    const int row0 = blockIdx.x * BM;
    const int ty = t >> 5, tx = t & 31;

    float acc[8][4];
#pragma unroll
    for (int i = 0; i < 8; ++i)
#pragma unroll
        for (int j = 0; j < 4; ++j) acc[i][j] = 0.f;

    auto load_stage = [&](int k, int buf) {
        if (t < BM) {
            int r = row0 + t;
            int idx = (r < N) ? nbr7[(size_t)k * N + r] : -1;
            float2 v = make_float2(0.f, 0.f);
            if (idx >= 0) v = *reinterpret_cast<const float2*>(&flow[(size_t)idx * 2]);
            sF[buf][t * 2] = v.x;
            sF[buf][t * 2 + 1] = v.y;
        }
        sW[buf][t] = W[(size_t)k * 256 + t];
    };

    load_stage(0, 0);
    for (int k = 0; k < KK; ++k) {
        __syncthreads();
        if (k + 1 < KK) load_stage(k + 1, (k + 1) & 1);
        const int buf = k & 1;
        float w0[4], w1[4];
#pragma unroll
        for (int j = 0; j < 4; ++j) {
            w0[j] = sW[buf][tx * 4 + j];
            w1[j] = sW[buf][128 + tx * 4 + j];
        }
#pragma unroll
        for (int i = 0; i < 8; ++i) {
            float f0 = sF[buf][(ty * 8 + i) * 2];
            float f1 = sF[buf][(ty * 8 + i) * 2 + 1];
#pragma unroll
            for (int j = 0; j < 4; ++j)
                acc[i][j] = fmaf(f0, w0[j], fmaf(f1, w1[j], acc[i][j]));
        }
    }
#pragma unroll
    for (int i = 0; i < 8; ++i) {
        int r = row0 + ty * 8 + i;
        if (r >= N) continue;
#pragma unroll
        for (int j = 0; j < 4; ++j) {
            int c = tx * 4 + j;
            out[(size_t)r * 128 + c] = fmaxf(acc[i][j] + bias[c], 0.f);
        }
    }
}

__global__ void tail_copy(const float* __restrict__ ext,
                          const float* __restrict__ flow,
                          float* __restrict__ out, int N)
{
    int i = blockIdx.x * blockDim.x + threadIdx.x;
    if (i >= N * 8) return;
    int r = i >> 3, c = i & 7;
    float v = (c < 2) ? flow[(size_t)r * 2 + c] : ext[(size_t)r * 6 + (c - 2)];
    out[(size_t)r * 128 + 120 + c] = v;
}

// ---------------------------------------------------------------------------
extern "C" void kernel_launch(void* const* d_in, const int* in_sizes, int n_in,
                              void* d_out, int out_size)
{
    const float* extr  = (const float*)d_in[0];
    const float* flow  = (const float*)d_in[1];
    const float* corrf = (const float*)d_in[2];
    const int*   nbr3  = (const int*)  d_in[3];
    const int*   nbr7  = (const int*)  d_in[4];
    const float* Wc1   = (const float*)d_in[5];
    const float* bc1   = (const float*)d_in[6];
    const float* Wc2   = (const float*)d_in[7];
    const float* bc2   = (const float*)d_in[8];
    const float* Wf1   = (const float*)d_in[9];
    const float* bf1   = (const float*)d_in[10];
    const float* Wf2   = (const float*)d_in[11];
    const float* bf2   = (const float*)d_in[12];
    const float* Wcat  = (const float*)d_in[13];
    const float* bcat  = (const float*)d_in[14];
    float* out = (float*)d_out;

    const int N = in_sizes[0] / 6;

    float *p_corr1, *p_f1, *p_cat;
    cudaGetSymbolAddress((void**)&p_corr1, g_corr1);
    cudaGetSymbolAddress((void**)&p_f1,    g_f1);
    cudaGetSymbolAddress((void**)&p_cat,   g_cat);
    __nv_bfloat16 *c1h, *c1l, *c2h, *c2l, *f2h, *f2l, *cth, *ctl;
    cudaGetSymbolAddress((void**)&c1h, gW_c1_hi);
    cudaGetSymbolAddress((void**)&c1l, gW_c1_lo);
    cudaGetSymbolAddress((void**)&c2h, gW_c2_hi);
    cudaGetSymbolAddress((void**)&c2l, gW_c2_lo);
    cudaGetSymbolAddress((void**)&f2h, gW_f2_hi);
    cudaGetSymbolAddress((void**)&f2l, gW_f2_lo);
    cudaGetSymbolAddress((void**)&cth, gW_ct_hi);
    cudaGetSymbolAddress((void**)&ctl, gW_ct_lo);

    // ---- weight prep ----
    prep_w<1, 324, 256, 352, 256><<<(1 * 256 * 352 + 255) / 256, 256>>>(Wc1, c1h, c1l);
    prep_w<27, 256, 192, 256, 192><<<(27 * 192 * 256 + 255) / 256, 256>>>(Wc2, c2h, c2l);
    prep_w<27, 128, 64, 128, 64><<<(27 * 64 * 128 + 255) / 256, 256>>>(Wf2, f2h, f2l);
    prep_w<27, 256, 120, 256, 128><<<(27 * 128 * 256 + 255) / 256, 256>>>(Wcat, cth, ctl);

    const int mblk = (N + 127) / 128;
    const int DSM = 30720;

    // corr1 = relu(corrf @ Wc1 + bc1)  (identity gather, COUT=256 -> 4 ytiles)
    tmma<1, 324, 352, 256><<<dim3(mblk, 4), 256, DSM>>>(
        corrf, 324, nullptr, c1h, c1l, bc1, p_corr1, 256, 0, 256, N);

    // f1 = relu(flow_conv)
    flow_conv<<<(N + 63) / 64, 256>>>(flow, nbr7, Wf1, bf1, p_f1, N);

    // cat[:,0:192]
    tmma<27, 256, 256, 192><<<dim3(mblk, 3), 256, DSM>>>(
        p_corr1, 256, nbr3, c2h, c2l, bc2, p_cat, 256, 0, 192, N);

    // cat[:,192:256]
    tmma<27, 128, 128, 64><<<dim3(mblk, 1), 256, DSM>>>(
        p_f1, 128, nbr3, f2h, f2l, bf2, p_cat, 256, 192, 64, N);

    // out[:,0:120]
    tmma<27, 256, 256, 128><<<dim3(mblk, 2), 256, DSM>>>(
        p_cat, 256, nbr3, cth, ctl, bcat, out, 128, 0, 120, N);

    tail_copy<<<(N * 8 + 255) / 256, 256>>>(extr, flow, out, N);
}

// round 5
// speedup vs baseline: 2.7581x; 1.0822x over previous
#include <cuda_runtime.h>
#include <cuda_bf16.h>
#include <cstdint>

// ===========================================================================
// SparseMotionEncoder — round 5: HMMA bf16x3 + ldmatrix + cp.async pipeline
//
//   corr1 = relu(corrf @ Wc1 + bc1)                 tmma<1,324>   NT=128 x2
//   cat[:,0:192]  = relu(conv(corr1,nbr3,Wc2))      tmma<27,256>  NT=96  x2
//   f1    = relu(conv(flow, nbr7, Wf1))             SIMT flow_conv
//   cat[:,192:256]= relu(conv(f1,  nbr3,Wf2))       tmma<27,128>  NT=64  x1
//   out[:,0:120]  = relu(conv(cat, nbr3,Wcat))      tmma<27,256>  NT=128 x1
//   out[:,120:128]= [flow, extrinsics]
//
// Numerics: x = hi + lo (bf16 each); D = Ah*Bh + Al*Bh + Ah*Bl, fp32 acc.
// Smem rows are 80 B (32 data halves + pad): conflict-free for ldmatrix.
// ===========================================================================

#define NVOX 50000

__device__ float g_corr1[NVOX * 256];
__device__ float g_f1[NVOX * 128];
__device__ float g_cat[NVOX * 256];

// Transposed, split weights: [KK][COUTPAD][CINPAD] bf16, zero padded.
__device__ __nv_bfloat16 gW_c1_hi[1 * 256 * 352], gW_c1_lo[1 * 256 * 352];
__device__ __nv_bfloat16 gW_c2_hi[27 * 192 * 256], gW_c2_lo[27 * 192 * 256];
__device__ __nv_bfloat16 gW_f2_hi[27 * 64 * 128],  gW_f2_lo[27 * 64 * 128];
__device__ __nv_bfloat16 gW_ct_hi[27 * 128 * 256], gW_ct_lo[27 * 128 * 256];

__device__ __forceinline__ uint32_t pkbf(float a, float b) {
    __nv_bfloat162 t = __floats2bfloat162_rn(a, b);
    return *reinterpret_cast<uint32_t*>(&t);
}

__device__ __forceinline__ void mma16816(float* c, const uint32_t* a,
                                         const uint32_t* b) {
    asm volatile(
        "mma.sync.aligned.m16n8k16.row.col.f32.bf16.bf16.f32 "
        "{%0,%1,%2,%3}, {%4,%5,%6,%7}, {%8,%9}, {%0,%1,%2,%3};"
        : "+f"(c[0]), "+f"(c[1]), "+f"(c[2]), "+f"(c[3])
        : "r"(a[0]), "r"(a[1]), "r"(a[2]), "r"(a[3]), "r"(b[0]), "r"(b[1]));
}

__device__ __forceinline__ void ldsm4(uint32_t* r, uint32_t addr) {
    asm volatile(
        "ldmatrix.sync.aligned.m8n8.x4.shared.b16 {%0,%1,%2,%3}, [%4];"
        : "=r"(r[0]), "=r"(r[1]), "=r"(r[2]), "=r"(r[3]) : "r"(addr));
}

__device__ __forceinline__ void cpasync16(uint32_t dst, const void* src) {
    asm volatile("cp.async.cg.shared.global [%0], [%1], 16;"
                 :: "r"(dst), "l"(src));
}
#define CP_COMMIT() asm volatile("cp.async.commit_group;" ::: "memory")
#define CP_WAIT0()  asm volatile("cp.async.wait_group 0;" ::: "memory")

// ---------------------------------------------------------------------------
// Weight prep: W[k][c][n] fp32 -> Wt_hi/lo[k][n][c] bf16, zero padded.
// ---------------------------------------------------------------------------
template <int KK, int CIN, int COUT, int CINPAD, int COUTPAD>
__global__ void prep_w(const float* __restrict__ W,
                       __nv_bfloat16* __restrict__ hi,
                       __nv_bfloat16* __restrict__ lo)
{
    long tid = (long)blockIdx.x * blockDim.x + threadIdx.x;
    const long total = (long)KK * COUTPAD * CINPAD;
    if (tid >= total) return;
    int c = tid % CINPAD;
    long r = tid / CINPAD;
    int n = r % COUTPAD;
    int k = r / COUTPAD;
    float x = (c < CIN && n < COUT) ? W[((size_t)k * CIN + c) * COUT + n] : 0.f;
    __nv_bfloat16 h = __float2bfloat16(x);
    hi[tid] = h;
    lo[tid] = __float2bfloat16(x - __bfloat162float(h));
}

// ---------------------------------------------------------------------------
// Pipelined HMMA gather-GEMM. CTA tile 128(M) x NT(N), BK=32, 256 threads,
// 8 warps in 4x2 grid, warp tile 32 x NT/2.
// 2-stage pipeline: A gathered into regs + cp.async B while computing.
// ---------------------------------------------------------------------------
template <int KK, int CIN, int CINPAD, int NT>
__global__ void __launch_bounds__(256)
tmma(const float* __restrict__ feat, int fstride, const int* __restrict__ nbr,
     const __nv_bfloat16* __restrict__ Whi, const __nv_bfloat16* __restrict__ Wlo,
     int COUTPAD, const float* __restrict__ bias, float* __restrict__ out,
     int ostride, int ocol, int COUT, int N)
{
    constexpr bool TAIL = (CIN % 32) != 0;
    constexpr int CH = CINPAD / 32;
    constexpr int ITERS = KK * CH;
    constexpr int WN = NT / 2;            // per-warp n width
    constexpr int J  = NT / 16;           // per-warp 8-col tiles
    constexpr int JP = J / 2;
    constexpr int BQ = (NT * 8) / 256;    // cp.async chunks per thread
    constexpr uint32_t AB = 10240;        // 128 rows * 80 B
    constexpr uint32_t BB = NT * 80;

    __shared__ int sIdx[KK][128];
    extern __shared__ char dyn[];
    const uint32_t sb = (uint32_t)__cvta_generic_to_shared(dyn);

    const int t = threadIdx.x, lane = t & 31, w = t >> 5;
    const int wm = w >> 1, wn = w & 1;
    const int g = lane >> 2, tg = lane & 3;
    const int row0 = blockIdx.x * 128;
    const int n0 = blockIdx.y * NT;

    for (int e = t; e < KK * 128; e += 256) {
        int k = e >> 7, m = e & 127;
        int r = row0 + m;
        sIdx[k][m] = (r < N) ? (nbr ? nbr[(size_t)k * N + r] : r) : -1;
    }

    float acc[2][J][4];
#pragma unroll
    for (int i = 0; i < 2; ++i)
#pragma unroll
        for (int j = 0; j < J; ++j)
#pragma unroll
            for (int q = 0; q < 4; ++q) acc[i][j][q] = 0.f;

    const int gr = t >> 1;            // gather row 0..127
    const int gcb = (t & 1) * 16;     // col base within 32-chunk

    __syncthreads();

    float4 va[4];

    auto gatherA = [&](int it) {
        const int k = it / CH, cc = it % CH;
        const int idx = sIdx[k][gr];
        const float* frow = (idx >= 0) ? feat + (size_t)idx * fstride : nullptr;
        const int c0 = cc * 32;
#pragma unroll
        for (int i = 0; i < 4; ++i) {
            const int gcol = c0 + gcb + i * 4;
            float4 v = make_float4(0.f, 0.f, 0.f, 0.f);
            if (frow) {
                if (!TAIL || gcol + 3 < CIN) {
                    v = *reinterpret_cast<const float4*>(frow + gcol);
                } else {
                    float tmp[4] = {0.f, 0.f, 0.f, 0.f};
#pragma unroll
                    for (int jj = 0; jj < 4; ++jj)
                        if (gcol + jj < CIN) tmp[jj] = frow[gcol + jj];
                    v = make_float4(tmp[0], tmp[1], tmp[2], tmp[3]);
                }
            }
            va[i] = v;
        }
    };

    auto storeA = [&](int stage) {
        char* base_h = dyn + (stage * 2 + 0) * AB;
        char* base_l = dyn + (stage * 2 + 1) * AB;
        const int roff = gr * 80;
#pragma unroll
        for (int i = 0; i < 4; ++i) {
            float4 v = va[i];
            float hx = __bfloat162float(__float2bfloat16(v.x));
            float hy = __bfloat162float(__float2bfloat16(v.y));
            float hz = __bfloat162float(__float2bfloat16(v.z));
            float hw = __bfloat162float(__float2bfloat16(v.w));
            uint2 uh = make_uint2(pkbf(hx, hy), pkbf(hz, hw));
            uint2 ul = make_uint2(pkbf(v.x - hx, v.y - hy),
                                  pkbf(v.z - hz, v.w - hw));
            const int boff = roff + (gcb + i * 4) * 2;
            *reinterpret_cast<uint2*>(base_h + boff) = uh;
            *reinterpret_cast<uint2*>(base_l + boff) = ul;
        }
    };

    auto issueB = [&](int it, int stage) {
        const int k = it / CH, cc = it % CH;
        const size_t base = ((size_t)k * COUTPAD + n0) * CINPAD + cc * 32;
#pragma unroll
        for (int q = 0; q < BQ; ++q) {
            const int e = t + q * 256;
            const int plane = e / (NT * 4);
            const int re = e - plane * (NT * 4);
            const int row = re >> 2, seg = re & 3;
            const __nv_bfloat16* src =
                (plane ? Wlo : Whi) + base + (size_t)row * CINPAD + seg * 8;
            const uint32_t dst =
                sb + 4 * AB + (uint32_t)(stage * 2 + plane) * BB + row * 80 + seg * 16;
            cpasync16(dst, src);
        }
    };

    // ---- prologue: fill stage 0 ----
    gatherA(0);
    issueB(0, 0);
    CP_COMMIT();
    storeA(0);
    CP_WAIT0();
    __syncthreads();

    const int local = lane & 7, grp = lane >> 3;
    const int arow = (grp & 1) * 8 + local;
    const int abyt = (grp >> 1) * 16;
    const int nloc = (grp >> 1) * 8 + local;
    const int bbyt = (grp & 1) * 16;

#pragma unroll 1
    for (int it = 0; it < ITERS; ++it) {
        const int cur = it & 1, nxt = cur ^ 1;
        const bool more = (it + 1 < ITERS);
        if (more) {
            gatherA(it + 1);
            issueB(it + 1, nxt);
            CP_COMMIT();
        }

        // ---- compute on stage cur ----
        const uint32_t aH = sb + (uint32_t)(cur * 2 + 0) * AB;
        const uint32_t aL = sb + (uint32_t)(cur * 2 + 1) * AB;
        const uint32_t bH = sb + 4 * AB + (uint32_t)(cur * 2 + 0) * BB;
        const uint32_t bL = sb + 4 * AB + (uint32_t)(cur * 2 + 1) * BB;
#pragma unroll
        for (int ks = 0; ks < 2; ++ks) {
            uint32_t Ah[2][4], Al[2][4];
#pragma unroll
            for (int i = 0; i < 2; ++i) {
                const uint32_t ao =
                    (uint32_t)((wm * 32 + i * 16 + arow) * 80 + ks * 32 + abyt);
                ldsm4(Ah[i], aH + ao);
                ldsm4(Al[i], aL + ao);
            }
#pragma unroll
            for (int jp = 0; jp < JP; ++jp) {
                const uint32_t bo =
                    (uint32_t)((wn * WN + jp * 16 + nloc) * 80 + ks * 32 + bbyt);
                uint32_t Bh[4], Bl[4];
                ldsm4(Bh, bH + bo);
                ldsm4(Bl, bL + bo);
#pragma unroll
                for (int i = 0; i < 2; ++i) {
                    mma16816(acc[i][2 * jp],     Ah[i], Bh);
                    mma16816(acc[i][2 * jp],     Al[i], Bh);
                    mma16816(acc[i][2 * jp],     Ah[i], Bl);
                    mma16816(acc[i][2 * jp + 1], Ah[i], Bh + 2);
                    mma16816(acc[i][2 * jp + 1], Al[i], Bh + 2);
                    mma16816(acc[i][2 * jp + 1], Ah[i], Bl + 2);
                }
            }
        }

        if (more) {
            storeA(nxt);
            CP_WAIT0();
        }
        __syncthreads();
    }

    // ---- epilogue: bias + relu -> global ----
#pragma unroll
    for (int j = 0; j < J; ++j) {
        const int col = n0 + wn * WN + j * 8 + tg * 2;
        if (col >= COUT) continue;
        const float2 bv = *reinterpret_cast<const float2*>(bias + col);
#pragma unroll
        for (int i = 0; i < 2; ++i) {
            const int r1 = row0 + wm * 32 + i * 16 + g;
            if (r1 < N) {
                float2 o = make_float2(fmaxf(acc[i][j][0] + bv.x, 0.f),
                                       fmaxf(acc[i][j][1] + bv.y, 0.f));
                *reinterpret_cast<float2*>(out + (size_t)r1 * ostride + ocol + col) = o;
            }
            const int r2 = r1 + 8;
            if (r2 < N) {
                float2 o = make_float2(fmaxf(acc[i][j][2] + bv.x, 0.f),
                                       fmaxf(acc[i][j][3] + bv.y, 0.f));
                *reinterpret_cast<float2*>(out + (size_t)r2 * ostride + ocol + col) = o;
            }
        }
    }
}

// ---------------------------------------------------------------------------
// Flow conv (K=343, Cin=2, Cout=128): SIMT, double-buffered.
// ---------------------------------------------------------------------------
__global__ void __launch_bounds__(256)
flow_conv(const float* __restrict__ flow, const int* __restrict__ nbr7,
          const float* __restrict__ W, const float* __restrict__ bias,
          float* __restrict__ out, int N)
{
    constexpr int KK = 343, BM = 64;
    __shared__ float sF[2][BM * 2];
    __shared__ float sW[2][256];

    const int t = threadIdx.x;
    const int row0 = blockIdx.x * BM;
    const int ty = t >> 5, tx = t & 31;

    float acc[8][4];
#pragma unroll
    for (int i = 0; i < 8; ++i)
#pragma unroll
        for (int j = 0; j < 4; ++j) acc[i][j] = 0.f;

    auto load_stage = [&](int k, int buf) {
        if (t < BM) {
            int r = row0 + t;
            int idx = (r < N) ? nbr7[(size_t)k * N + r] : -1;
            float2 v = make_float2(0.f, 0.f);
            if (idx >= 0) v = *reinterpret_cast<const float2*>(&flow[(size_t)idx * 2]);
            sF[buf][t * 2] = v.x;
            sF[buf][t * 2 + 1] = v.y;
        }
        sW[buf][t] = W[(size_t)k * 256 + t];
    };

    load_stage(0, 0);
    for (int k = 0; k < KK; ++k) {
        __syncthreads();
        if (k + 1 < KK) load_stage(k + 1, (k + 1) & 1);
        const int buf = k & 1;
        float w0[4], w1[4];
#pragma unroll
        for (int j = 0; j < 4; ++j) {
            w0[j] = sW[buf][tx * 4 + j];
            w1[j] = sW[buf][128 + tx * 4 + j];
        }
#pragma unroll
        for (int i = 0; i < 8; ++i) {
            float f0 = sF[buf][(ty * 8 + i) * 2];
            float f1 = sF[buf][(ty * 8 + i) * 2 + 1];
#pragma unroll
            for (int j = 0; j < 4; ++j)
                acc[i][j] = fmaf(f0, w0[j], fmaf(f1, w1[j], acc[i][j]));
        }
    }
#pragma unroll
    for (int i = 0; i < 8; ++i) {
        int r = row0 + ty * 8 + i;
        if (r >= N) continue;
#pragma unroll
        for (int j = 0; j < 4; ++j) {
            int c = tx * 4 + j;
            out[(size_t)r * 128 + c] = fmaxf(acc[i][j] + bias[c], 0.f);
        }
    }
}

__global__ void tail_copy(const float* __restrict__ ext,
                          const float* __restrict__ flow,
                          float* __restrict__ out, int N)
{
    int i = blockIdx.x * blockDim.x + threadIdx.x;
    if (i >= N * 8) return;
    int r = i >> 3, c = i & 7;
    float v = (c < 2) ? flow[(size_t)r * 2 + c] : ext[(size_t)r * 6 + (c - 2)];
    out[(size_t)r * 128 + 120 + c] = v;
}

// ---------------------------------------------------------------------------
extern "C" void kernel_launch(void* const* d_in, const int* in_sizes, int n_in,
                              void* d_out, int out_size)
{
    const float* extr  = (const float*)d_in[0];
    const float* flow  = (const float*)d_in[1];
    const float* corrf = (const float*)d_in[2];
    const int*   nbr3  = (const int*)  d_in[3];
    const int*   nbr7  = (const int*)  d_in[4];
    const float* Wc1   = (const float*)d_in[5];
    const float* bc1   = (const float*)d_in[6];
    const float* Wc2   = (const float*)d_in[7];
    const float* bc2   = (const float*)d_in[8];
    const float* Wf1   = (const float*)d_in[9];
    const float* bf1   = (const float*)d_in[10];
    const float* Wf2   = (const float*)d_in[11];
    const float* bf2   = (const float*)d_in[12];
    const float* Wcat  = (const float*)d_in[13];
    const float* bcat  = (const float*)d_in[14];
    float* out = (float*)d_out;

    const int N = in_sizes[0] / 6;

    float *p_corr1, *p_f1, *p_cat;
    cudaGetSymbolAddress((void**)&p_corr1, g_corr1);
    cudaGetSymbolAddress((void**)&p_f1,    g_f1);
    cudaGetSymbolAddress((void**)&p_cat,   g_cat);
    __nv_bfloat16 *c1h, *c1l, *c2h, *c2l, *f2h, *f2l, *cth, *ctl;
    cudaGetSymbolAddress((void**)&c1h, gW_c1_hi);
    cudaGetSymbolAddress((void**)&c1l, gW_c1_lo);
    cudaGetSymbolAddress((void**)&c2h, gW_c2_hi);
    cudaGetSymbolAddress((void**)&c2l, gW_c2_lo);
    cudaGetSymbolAddress((void**)&f2h, gW_f2_hi);
    cudaGetSymbolAddress((void**)&f2l, gW_f2_lo);
    cudaGetSymbolAddress((void**)&cth, gW_ct_hi);
    cudaGetSymbolAddress((void**)&ctl, gW_ct_lo);

    // ---- weight prep ----
    prep_w<1, 324, 256, 352, 256><<<(1 * 256 * 352 + 255) / 256, 256>>>(Wc1, c1h, c1l);
    prep_w<27, 256, 192, 256, 192><<<(27 * 192 * 256 + 255) / 256, 256>>>(Wc2, c2h, c2l);
    prep_w<27, 128, 64, 128, 64><<<(27 * 64 * 128 + 255) / 256, 256>>>(Wf2, f2h, f2l);
    prep_w<27, 256, 120, 256, 128><<<(27 * 128 * 256 + 255) / 256, 256>>>(Wcat, cth, ctl);

    const int mblk = (N + 127) / 128;
    auto dsm = [](int NT) { return 4 * 10240 + 4 * NT * 80; };

    cudaFuncSetAttribute(tmma<1, 324, 352, 128>,
                         cudaFuncAttributeMaxDynamicSharedMemorySize, dsm(128));
    cudaFuncSetAttribute(tmma<27, 256, 256, 96>,
                         cudaFuncAttributeMaxDynamicSharedMemorySize, dsm(96));
    cudaFuncSetAttribute(tmma<27, 128, 128, 64>,
                         cudaFuncAttributeMaxDynamicSharedMemorySize, dsm(64));
    cudaFuncSetAttribute(tmma<27, 256, 256, 128>,
                         cudaFuncAttributeMaxDynamicSharedMemorySize, dsm(128));

    // corr1 = relu(corrf @ Wc1 + bc1)  (identity gather)
    tmma<1, 324, 352, 128><<<dim3(mblk, 2), 256, dsm(128)>>>(
        corrf, 324, nullptr, c1h, c1l, 256, bc1, p_corr1, 256, 0, 256, N);

    // f1 = relu(flow_conv)
    flow_conv<<<(N + 63) / 64, 256>>>(flow, nbr7, Wf1, bf1, p_f1, N);

    // cat[:,0:192]
    tmma<27, 256, 256, 96><<<dim3(mblk, 2), 256, dsm(96)>>>(
        p_corr1, 256, nbr3, c2h, c2l, 192, bc2, p_cat, 256, 0, 192, N);

    // cat[:,192:256]
    tmma<27, 128, 128, 64><<<dim3(mblk, 1), 256, dsm(64)>>>(
        p_f1, 128, nbr3, f2h, f2l, 64, bf2, p_cat, 256, 192, 64, N);

    // out[:,0:120]
    tmma<27, 256, 256, 128><<<dim3(mblk, 1), 256, dsm(128)>>>(
        p_cat, 256, nbr3, cth, ctl, 128, bcat, out, 128, 0, 120, N);

    tail_copy<<<(N * 8 + 255) / 256, 256>>>(extr, flow, out, N);
}

// round 6
// speedup vs baseline: 5.3595x; 1.9432x over previous
#include <cuda_runtime.h>
#include <cuda_bf16.h>
#include <cstdint>

// ===========================================================================
// SparseMotionEncoder — round 6: sparsity-aware rulebook gather-GEMMs.
// Grid is ~19% occupied -> per-tap compacted (in,out) pair lists; each tap is
// a dense HMMA bf16x3 GEMM over only valid pairs, accumulated into a
// bias-initialized fp32 buffer via atomicAdd, then ReLU.
//
//   corr1 = relu(corrf @ Wc1 + bc1)              dense tmma (identity)
//   f1    = relu(conv(flow, nbr7, Wf1))          SIMT flow_conv (+warp skip)
//   cat[:,0:192]   = relu(conv(corr1,nbr3,Wc2))  tap_mma over list3
//   cat[:,192:256] = relu(conv(f1,  nbr3,Wf2))   tap_mma over list3
//   out[:,0:120]   = relu(conv(cat, nbr3,Wcat))  tap_mma over list3
//   out[:,120:128] = [flow, extrinsics]
// ===========================================================================

#define NVOX 50000

__device__ float g_corr1[NVOX * 256];
__device__ float g_f1[NVOX * 128];
__device__ float g_cat[NVOX * 256];

__device__ int  g_cnt3[27];
__device__ int2 g_list3[27 * NVOX];     // (in_idx, out_idx) per tap

// Transposed, split weights: [KK][COUTPAD][CINPAD] bf16, zero padded.
__device__ __nv_bfloat16 gW_c1_hi[1 * 256 * 352], gW_c1_lo[1 * 256 * 352];
__device__ __nv_bfloat16 gW_c2_hi[27 * 192 * 256], gW_c2_lo[27 * 192 * 256];
__device__ __nv_bfloat16 gW_f2_hi[27 * 64 * 128],  gW_f2_lo[27 * 64 * 128];
__device__ __nv_bfloat16 gW_ct_hi[27 * 128 * 256], gW_ct_lo[27 * 128 * 256];

__device__ __forceinline__ uint32_t pkbf(float a, float b) {
    __nv_bfloat162 t = __floats2bfloat162_rn(a, b);
    return *reinterpret_cast<uint32_t*>(&t);
}
__device__ __forceinline__ void mma16816(float* c, const uint32_t* a,
                                         const uint32_t* b) {
    asm volatile(
        "mma.sync.aligned.m16n8k16.row.col.f32.bf16.bf16.f32 "
        "{%0,%1,%2,%3}, {%4,%5,%6,%7}, {%8,%9}, {%0,%1,%2,%3};"
        : "+f"(c[0]), "+f"(c[1]), "+f"(c[2]), "+f"(c[3])
        : "r"(a[0]), "r"(a[1]), "r"(a[2]), "r"(a[3]), "r"(b[0]), "r"(b[1]));
}
__device__ __forceinline__ void ldsm4(uint32_t* r, uint32_t addr) {
    asm volatile(
        "ldmatrix.sync.aligned.m8n8.x4.shared.b16 {%0,%1,%2,%3}, [%4];"
        : "=r"(r[0]), "=r"(r[1]), "=r"(r[2]), "=r"(r[3]) : "r"(addr));
}
__device__ __forceinline__ void cpasync16(uint32_t dst, const void* src) {
    asm volatile("cp.async.cg.shared.global [%0], [%1], 16;" :: "r"(dst), "l"(src));
}
#define CP_COMMIT() asm volatile("cp.async.commit_group;" ::: "memory")
#define CP_WAIT0()  asm volatile("cp.async.wait_group 0;" ::: "memory")

// ---------------------------------------------------------------------------
template <int KK, int CIN, int COUT, int CINPAD, int COUTPAD>
__global__ void prep_w(const float* __restrict__ W,
                       __nv_bfloat16* __restrict__ hi,
                       __nv_bfloat16* __restrict__ lo)
{
    long tid = (long)blockIdx.x * blockDim.x + threadIdx.x;
    const long total = (long)KK * COUTPAD * CINPAD;
    if (tid >= total) return;
    int c = tid % CINPAD;
    long r = tid / CINPAD;
    int n = r % COUTPAD;
    int k = r / COUTPAD;
    float x = (c < CIN && n < COUT) ? W[((size_t)k * CIN + c) * COUT + n] : 0.f;
    __nv_bfloat16 h = __float2bfloat16(x);
    hi[tid] = h;
    lo[tid] = __float2bfloat16(x - __bfloat162float(h));
}

// ---------------------------------------------------------------------------
__global__ void zero_cnt() { if (threadIdx.x < 27) g_cnt3[threadIdx.x] = 0; }

__global__ void build_list(const int* __restrict__ nbr, int N)
{
    const int k = blockIdx.y;
    const int n = blockIdx.x * 256 + threadIdx.x;
    const int lane = threadIdx.x & 31;
    int idx = -1;
    if (n < N) idx = nbr[(size_t)k * N + n];
    const bool v = idx >= 0;
    unsigned m = __ballot_sync(0xffffffffu, v);
    if (!m) return;
    int leader = __ffs(m) - 1;
    int base = 0;
    if (lane == leader) base = atomicAdd(&g_cnt3[k], __popc(m));
    base = __shfl_sync(0xffffffffu, base, leader);
    if (v) {
        int pos = base + __popc(m & ((1u << lane) - 1u));
        g_list3[(size_t)k * NVOX + pos] = make_int2(idx, n);
    }
}

// ---------------------------------------------------------------------------
__global__ void init_bias(float* __restrict__ out, int ostride, int ocol,
                          const float* __restrict__ bias, int COUT, int N)
{
    long i = (long)blockIdx.x * blockDim.x + threadIdx.x;
    if (i >= (long)N * COUT) return;
    int r = i / COUT, c = i % COUT;
    out[(size_t)r * ostride + ocol + c] = bias[c];
}

__global__ void relu_region(float* __restrict__ p, int stride, int ocol,
                            int COUT, int N)
{
    long i = (long)blockIdx.x * blockDim.x + threadIdx.x;
    if (i >= (long)N * COUT) return;
    int r = i / COUT, c = i % COUT;
    float* q = p + (size_t)r * stride + ocol + c;
    *q = fmaxf(*q, 0.f);
}

// ---------------------------------------------------------------------------
// Dense pipelined HMMA gather-GEMM (identity gather) — used for c1 only.
// ---------------------------------------------------------------------------
template <int KK, int CIN, int CINPAD, int NT>
__global__ void __launch_bounds__(256)
tmma(const float* __restrict__ feat, int fstride,
     const __nv_bfloat16* __restrict__ Whi, const __nv_bfloat16* __restrict__ Wlo,
     int COUTPAD, const float* __restrict__ bias, float* __restrict__ out,
     int ostride, int ocol, int COUT, int N)
{
    constexpr bool TAIL = (CIN % 32) != 0;
    constexpr int CH = CINPAD / 32;
    constexpr int ITERS = KK * CH;
    constexpr int WN = NT / 2;
    constexpr int J  = NT / 16;
    constexpr int JP = J / 2;
    constexpr int BQ = (NT * 8) / 256;
    constexpr uint32_t AB = 10240;
    constexpr uint32_t BB = NT * 80;

    extern __shared__ char dyn[];
    const uint32_t sb = (uint32_t)__cvta_generic_to_shared(dyn);

    const int t = threadIdx.x, lane = t & 31, w = t >> 5;
    const int wm = w >> 1, wn = w & 1;
    const int g = lane >> 2, tg = lane & 3;
    const int row0 = blockIdx.x * 128;
    const int n0 = blockIdx.y * NT;

    float acc[2][J][4];
#pragma unroll
    for (int i = 0; i < 2; ++i)
#pragma unroll
        for (int j = 0; j < J; ++j)
#pragma unroll
            for (int q = 0; q < 4; ++q) acc[i][j][q] = 0.f;

    const int gr = t >> 1;
    const int gcb = (t & 1) * 16;
    const int grow = row0 + gr;

    float4 va[4];

    auto gatherA = [&](int it) {
        const int cc = it % CH;
        const float* frow = (grow < N) ? feat + (size_t)grow * fstride : nullptr;
        const int c0 = cc * 32;
#pragma unroll
        for (int i = 0; i < 4; ++i) {
            const int gcol = c0 + gcb + i * 4;
            float4 v = make_float4(0.f, 0.f, 0.f, 0.f);
            if (frow) {
                if (!TAIL || gcol + 3 < CIN) {
                    v = *reinterpret_cast<const float4*>(frow + gcol);
                } else {
                    float tmp[4] = {0.f, 0.f, 0.f, 0.f};
#pragma unroll
                    for (int jj = 0; jj < 4; ++jj)
                        if (gcol + jj < CIN) tmp[jj] = frow[gcol + jj];
                    v = make_float4(tmp[0], tmp[1], tmp[2], tmp[3]);
                }
            }
            va[i] = v;
        }
    };

    auto storeA = [&](int stage) {
        char* base_h = dyn + (stage * 2 + 0) * AB;
        char* base_l = dyn + (stage * 2 + 1) * AB;
        const int roff = gr * 80;
#pragma unroll
        for (int i = 0; i < 4; ++i) {
            float4 v = va[i];
            float hx = __bfloat162float(__float2bfloat16(v.x));
            float hy = __bfloat162float(__float2bfloat16(v.y));
            float hz = __bfloat162float(__float2bfloat16(v.z));
            float hw = __bfloat162float(__float2bfloat16(v.w));
            uint2 uh = make_uint2(pkbf(hx, hy), pkbf(hz, hw));
            uint2 ul = make_uint2(pkbf(v.x - hx, v.y - hy),
                                  pkbf(v.z - hz, v.w - hw));
            const int boff = roff + (gcb + i * 4) * 2;
            *reinterpret_cast<uint2*>(base_h + boff) = uh;
            *reinterpret_cast<uint2*>(base_l + boff) = ul;
        }
    };

    auto issueB = [&](int it, int stage) {
        const int k = it / CH, cc = it % CH;
        const size_t base = ((size_t)k * COUTPAD + n0) * CINPAD + cc * 32;
#pragma unroll
        for (int q = 0; q < BQ; ++q) {
            const int e = t + q * 256;
            const int plane = e / (NT * 4);
            const int re = e - plane * (NT * 4);
            const int row = re >> 2, seg = re & 3;
            const __nv_bfloat16* src =
                (plane ? Wlo : Whi) + base + (size_t)row * CINPAD + seg * 8;
            const uint32_t dst =
                sb + 4 * AB + (uint32_t)(stage * 2 + plane) * BB + row * 80 + seg * 16;
            cpasync16(dst, src);
        }
    };

    gatherA(0);
    issueB(0, 0);
    CP_COMMIT();
    storeA(0);
    CP_WAIT0();
    __syncthreads();

    const int local = lane & 7, grp = lane >> 3;
    const int arow = (grp & 1) * 8 + local;
    const int abyt = (grp >> 1) * 16;
    const int nloc = (grp >> 1) * 8 + local;
    const int bbyt = (grp & 1) * 16;

#pragma unroll 1
    for (int it = 0; it < ITERS; ++it) {
        const int cur = it & 1, nxt = cur ^ 1;
        const bool more = (it + 1 < ITERS);
        if (more) {
            gatherA(it + 1);
            issueB(it + 1, nxt);
            CP_COMMIT();
        }
        const uint32_t aH = sb + (uint32_t)(cur * 2 + 0) * AB;
        const uint32_t aL = sb + (uint32_t)(cur * 2 + 1) * AB;
        const uint32_t bH = sb + 4 * AB + (uint32_t)(cur * 2 + 0) * BB;
        const uint32_t bL = sb + 4 * AB + (uint32_t)(cur * 2 + 1) * BB;
#pragma unroll
        for (int ks = 0; ks < 2; ++ks) {
            uint32_t Ah[2][4], Al[2][4];
#pragma unroll
            for (int i = 0; i < 2; ++i) {
                const uint32_t ao =
                    (uint32_t)((wm * 32 + i * 16 + arow) * 80 + ks * 32 + abyt);
                ldsm4(Ah[i], aH + ao);
                ldsm4(Al[i], aL + ao);
            }
#pragma unroll
            for (int jp = 0; jp < JP; ++jp) {
                const uint32_t bo =
                    (uint32_t)((wn * WN + jp * 16 + nloc) * 80 + ks * 32 + bbyt);
                uint32_t Bh[4], Bl[4];
                ldsm4(Bh, bH + bo);
                ldsm4(Bl, bL + bo);
#pragma unroll
                for (int i = 0; i < 2; ++i) {
                    mma16816(acc[i][2 * jp],     Ah[i], Bh);
                    mma16816(acc[i][2 * jp],     Al[i], Bh);
                    mma16816(acc[i][2 * jp],     Ah[i], Bl);
                    mma16816(acc[i][2 * jp + 1], Ah[i], Bh + 2);
                    mma16816(acc[i][2 * jp + 1], Al[i], Bh + 2);
                    mma16816(acc[i][2 * jp + 1], Ah[i], Bl + 2);
                }
            }
        }
        if (more) {
            storeA(nxt);
            CP_WAIT0();
        }
        __syncthreads();
    }

#pragma unroll
    for (int j = 0; j < J; ++j) {
        const int col = n0 + wn * WN + j * 8 + tg * 2;
        if (col >= COUT) continue;
        const float2 bv = *reinterpret_cast<const float2*>(bias + col);
#pragma unroll
        for (int i = 0; i < 2; ++i) {
            const int r1 = row0 + wm * 32 + i * 16 + g;
            if (r1 < N) {
                float2 o = make_float2(fmaxf(acc[i][j][0] + bv.x, 0.f),
                                       fmaxf(acc[i][j][1] + bv.y, 0.f));
                *reinterpret_cast<float2*>(out + (size_t)r1 * ostride + ocol + col) = o;
            }
            const int r2 = r1 + 8;
            if (r2 < N) {
                float2 o = make_float2(fmaxf(acc[i][j][2] + bv.x, 0.f),
                                       fmaxf(acc[i][j][3] + bv.y, 0.f));
                *reinterpret_cast<float2*>(out + (size_t)r2 * ostride + ocol + col) = o;
            }
        }
    }
}

// ---------------------------------------------------------------------------
// Per-tap rulebook HMMA GEMM: rows = compacted (in,out) pairs for tap
// blockIdx.z; accumulate into out via atomicAdd (bias pre-initialized).
// ---------------------------------------------------------------------------
template <int CIN, int CINPAD, int NT>
__global__ void __launch_bounds__(256)
tap_mma(const float* __restrict__ feat, int fstride,
        const __nv_bfloat16* __restrict__ Whi, const __nv_bfloat16* __restrict__ Wlo,
        int COUTPAD, float* __restrict__ out, int ostride, int ocol, int COUT)
{
    constexpr int CH = CINPAD / 32;
    constexpr int ITERS = CH;
    constexpr int WN = NT / 2;
    constexpr int J  = NT / 16;
    constexpr int JP = J / 2;
    constexpr int BQ = (NT * 8) / 256;
    constexpr uint32_t AB = 10240;
    constexpr uint32_t BB = NT * 80;

    const int tap = blockIdx.z;
    const int cn = g_cnt3[tap];
    const int m0 = blockIdx.x * 128;
    if (m0 >= cn) return;
    const int n0 = blockIdx.y * NT;

    __shared__ int sIn[128], sOut[128];
    extern __shared__ char dyn[];
    const uint32_t sb = (uint32_t)__cvta_generic_to_shared(dyn);

    const int t = threadIdx.x, lane = t & 31, w = t >> 5;
    const int wm = w >> 1, wn = w & 1;
    const int g = lane >> 2, tg = lane & 3;

    if (t < 128) {
        const int m = m0 + t;
        if (m < cn) {
            int2 p = g_list3[(size_t)tap * NVOX + m];
            sIn[t] = p.x;
            sOut[t] = p.y;
        } else {
            sIn[t] = -1;
            sOut[t] = -1;
        }
    }
    __syncthreads();

    float acc[2][J][4];
#pragma unroll
    for (int i = 0; i < 2; ++i)
#pragma unroll
        for (int j = 0; j < J; ++j)
#pragma unroll
            for (int q = 0; q < 4; ++q) acc[i][j][q] = 0.f;

    const int gr = t >> 1;
    const int gcb = (t & 1) * 16;
    const int gin = sIn[gr];
    const float* frow = (gin >= 0) ? feat + (size_t)gin * fstride : nullptr;

    float4 va[4];
    auto gatherA = [&](int it) {
        const int c0 = it * 32;
#pragma unroll
        for (int i = 0; i < 4; ++i) {
            float4 v = make_float4(0.f, 0.f, 0.f, 0.f);
            if (frow) v = *reinterpret_cast<const float4*>(frow + c0 + gcb + i * 4);
            va[i] = v;
        }
    };
    auto storeA = [&](int stage) {
        char* base_h = dyn + (stage * 2 + 0) * AB;
        char* base_l = dyn + (stage * 2 + 1) * AB;
        const int roff = gr * 80;
#pragma unroll
        for (int i = 0; i < 4; ++i) {
            float4 v = va[i];
            float hx = __bfloat162float(__float2bfloat16(v.x));
            float hy = __bfloat162float(__float2bfloat16(v.y));
            float hz = __bfloat162float(__float2bfloat16(v.z));
            float hw = __bfloat162float(__float2bfloat16(v.w));
            uint2 uh = make_uint2(pkbf(hx, hy), pkbf(hz, hw));
            uint2 ul = make_uint2(pkbf(v.x - hx, v.y - hy),
                                  pkbf(v.z - hz, v.w - hw));
            const int boff = roff + (gcb + i * 4) * 2;
            *reinterpret_cast<uint2*>(base_h + boff) = uh;
            *reinterpret_cast<uint2*>(base_l + boff) = ul;
        }
    };
    auto issueB = [&](int it, int stage) {
        const size_t base = ((size_t)tap * COUTPAD + n0) * CINPAD + it * 32;
#pragma unroll
        for (int q = 0; q < BQ; ++q) {
            const int e = t + q * 256;
            const int plane = e / (NT * 4);
            const int re = e - plane * (NT * 4);
            const int row = re >> 2, seg = re & 3;
            const __nv_bfloat16* src =
                (plane ? Wlo : Whi) + base + (size_t)row * CINPAD + seg * 8;
            const uint32_t dst =
                sb + 4 * AB + (uint32_t)(stage * 2 + plane) * BB + row * 80 + seg * 16;
            cpasync16(dst, src);
        }
    };

    gatherA(0);
    issueB(0, 0);
    CP_COMMIT();
    storeA(0);
    CP_WAIT0();
    __syncthreads();

    const int local = lane & 7, grp = lane >> 3;
    const int arow = (grp & 1) * 8 + local;
    const int abyt = (grp >> 1) * 16;
    const int nloc = (grp >> 1) * 8 + local;
    const int bbyt = (grp & 1) * 16;

#pragma unroll 1
    for (int it = 0; it < ITERS; ++it) {
        const int cur = it & 1, nxt = cur ^ 1;
        const bool more = (it + 1 < ITERS);
        if (more) {
            gatherA(it + 1);
            issueB(it + 1, nxt);
            CP_COMMIT();
        }
        const uint32_t aH = sb + (uint32_t)(cur * 2 + 0) * AB;
        const uint32_t aL = sb + (uint32_t)(cur * 2 + 1) * AB;
        const uint32_t bH = sb + 4 * AB + (uint32_t)(cur * 2 + 0) * BB;
        const uint32_t bL = sb + 4 * AB + (uint32_t)(cur * 2 + 1) * BB;
#pragma unroll
        for (int ks = 0; ks < 2; ++ks) {
            uint32_t Ah[2][4], Al[2][4];
#pragma unroll
            for (int i = 0; i < 2; ++i) {
                const uint32_t ao =
                    (uint32_t)((wm * 32 + i * 16 + arow) * 80 + ks * 32 + abyt);
                ldsm4(Ah[i], aH + ao);
                ldsm4(Al[i], aL + ao);
            }
#pragma unroll
            for (int jp = 0; jp < JP; ++jp) {
                const uint32_t bo =
                    (uint32_t)((wn * WN + jp * 16 + nloc) * 80 + ks * 32 + bbyt);
                uint32_t Bh[4], Bl[4];
                ldsm4(Bh, bH + bo);
                ldsm4(Bl, bL + bo);
#pragma unroll
                for (int i = 0; i < 2; ++i) {
                    mma16816(acc[i][2 * jp],     Ah[i], Bh);
                    mma16816(acc[i][2 * jp],     Al[i], Bh);
                    mma16816(acc[i][2 * jp],     Ah[i], Bl);
                    mma16816(acc[i][2 * jp + 1], Ah[i], Bh + 2);
                    mma16816(acc[i][2 * jp + 1], Al[i], Bh + 2);
                    mma16816(acc[i][2 * jp + 1], Ah[i], Bl + 2);
                }
            }
        }
        if (more) {
            storeA(nxt);
            CP_WAIT0();
        }
        __syncthreads();
    }

    // ---- epilogue: atomic accumulate into out rows ----
#pragma unroll
    for (int j = 0; j < J; ++j) {
        const int col = n0 + wn * WN + j * 8 + tg * 2;
        if (col >= COUT) continue;
#pragma unroll
        for (int i = 0; i < 2; ++i) {
            const int lr1 = wm * 32 + i * 16 + g;
            const int ro1 = sOut[lr1];
            if (ro1 >= 0) {
                float* p = out + (size_t)ro1 * ostride + ocol + col;
                atomicAdd(p, acc[i][j][0]);
                atomicAdd(p + 1, acc[i][j][1]);
            }
            const int ro2 = sOut[lr1 + 8];
            if (ro2 >= 0) {
                float* p = out + (size_t)ro2 * ostride + ocol + col;
                atomicAdd(p, acc[i][j][2]);
                atomicAdd(p + 1, acc[i][j][3]);
            }
        }
    }
}

// ---------------------------------------------------------------------------
// Flow conv (K=343, Cin=2, Cout=128): SIMT, double-buffered, per-warp tap skip.
// ---------------------------------------------------------------------------
__global__ void __launch_bounds__(256)
flow_conv(const float* __restrict__ flow, const int* __restrict__ nbr7,
          const float* __restrict__ W, const float* __restrict__ bias,
          float* __restrict__ out, int N)
{
    constexpr int KK = 343, BM = 64;
    __shared__ float sF[2][BM * 2];
    __shared__ float sW[2][256];
    __shared__ unsigned char sV[2][BM];

    const int t = threadIdx.x;
    const int row0 = blockIdx.x * BM;
    const int ty = t >> 5, tx = t & 31;

    float acc[8][4];
#pragma unroll
    for (int i = 0; i < 8; ++i)
#pragma unroll
        for (int j = 0; j < 4; ++j) acc[i][j] = 0.f;

    auto load_stage = [&](int k, int buf) {
        if (t < BM) {
            int r = row0 + t;
            int idx = (r < N) ? nbr7[(size_t)k * N + r] : -1;
            float2 v = make_float2(0.f, 0.f);
            if (idx >= 0) v = *reinterpret_cast<const float2*>(&flow[(size_t)idx * 2]);
            sF[buf][t * 2] = v.x;
            sF[buf][t * 2 + 1] = v.y;
            sV[buf][t] = (idx >= 0);
        }
        sW[buf][t] = W[(size_t)k * 256 + t];
    };

    load_stage(0, 0);
    for (int k = 0; k < KK; ++k) {
        __syncthreads();
        if (k + 1 < KK) load_stage(k + 1, (k + 1) & 1);
        const int buf = k & 1;
        const bool myv = (tx < 8) && (sV[buf][ty * 8 + tx] != 0);
        if (__ballot_sync(0xffffffffu, myv)) {
            float w0[4], w1[4];
#pragma unroll
            for (int j = 0; j < 4; ++j) {
                w0[j] = sW[buf][tx * 4 + j];
                w1[j] = sW[buf][128 + tx * 4 + j];
            }
#pragma unroll
            for (int i = 0; i < 8; ++i) {
                float f0 = sF[buf][(ty * 8 + i) * 2];
                float f1 = sF[buf][(ty * 8 + i) * 2 + 1];
#pragma unroll
                for (int j = 0; j < 4; ++j)
                    acc[i][j] = fmaf(f0, w0[j], fmaf(f1, w1[j], acc[i][j]));
            }
        }
    }
#pragma unroll
    for (int i = 0; i < 8; ++i) {
        int r = row0 + ty * 8 + i;
        if (r >= N) continue;
#pragma unroll
        for (int j = 0; j < 4; ++j) {
            int c = tx * 4 + j;
            out[(size_t)r * 128 + c] = fmaxf(acc[i][j] + bias[c], 0.f);
        }
    }
}

__global__ void tail_copy(const float* __restrict__ ext,
                          const float* __restrict__ flow,
                          float* __restrict__ out, int N)
{
    int i = blockIdx.x * blockDim.x + threadIdx.x;
    if (i >= N * 8) return;
    int r = i >> 3, c = i & 7;
    float v = (c < 2) ? flow[(size_t)r * 2 + c] : ext[(size_t)r * 6 + (c - 2)];
    out[(size_t)r * 128 + 120 + c] = v;
}

// ---------------------------------------------------------------------------
extern "C" void kernel_launch(void* const* d_in, const int* in_sizes, int n_in,
                              void* d_out, int out_size)
{
    const float* extr  = (const float*)d_in[0];
    const float* flow  = (const float*)d_in[1];
    const float* corrf = (const float*)d_in[2];
    const int*   nbr3  = (const int*)  d_in[3];
    const int*   nbr7  = (const int*)  d_in[4];
    const float* Wc1   = (const float*)d_in[5];
    const float* bc1   = (const float*)d_in[6];
    const float* Wc2   = (const float*)d_in[7];
    const float* bc2   = (const float*)d_in[8];
    const float* Wf1   = (const float*)d_in[9];
    const float* bf1   = (const float*)d_in[10];
    const float* Wf2   = (const float*)d_in[11];
    const float* bf2   = (const float*)d_in[12];
    const float* Wcat  = (const float*)d_in[13];
    const float* bcat  = (const float*)d_in[14];
    float* out = (float*)d_out;

    const int N = in_sizes[0] / 6;

    float *p_corr1, *p_f1, *p_cat;
    cudaGetSymbolAddress((void**)&p_corr1, g_corr1);
    cudaGetSymbolAddress((void**)&p_f1,    g_f1);
    cudaGetSymbolAddress((void**)&p_cat,   g_cat);
    __nv_bfloat16 *c1h, *c1l, *c2h, *c2l, *f2h, *f2l, *cth, *ctl;
    cudaGetSymbolAddress((void**)&c1h, gW_c1_hi);
    cudaGetSymbolAddress((void**)&c1l, gW_c1_lo);
    cudaGetSymbolAddress((void**)&c2h, gW_c2_hi);
    cudaGetSymbolAddress((void**)&c2l, gW_c2_lo);
    cudaGetSymbolAddress((void**)&f2h, gW_f2_hi);
    cudaGetSymbolAddress((void**)&f2l, gW_f2_lo);
    cudaGetSymbolAddress((void**)&cth, gW_ct_hi);
    cudaGetSymbolAddress((void**)&ctl, gW_ct_lo);

    // ---- weight prep + rulebook build ----
    prep_w<1, 324, 256, 352, 256><<<(1 * 256 * 352 + 255) / 256, 256>>>(Wc1, c1h, c1l);
    prep_w<27, 256, 192, 256, 192><<<(27 * 192 * 256 + 255) / 256, 256>>>(Wc2, c2h, c2l);
    prep_w<27, 128, 64, 128, 64><<<(27 * 64 * 128 + 255) / 256, 256>>>(Wf2, f2h, f2l);
    prep_w<27, 256, 120, 256, 128><<<(27 * 128 * 256 + 255) / 256, 256>>>(Wcat, cth, ctl);
    zero_cnt<<<1, 32>>>();
    build_list<<<dim3((N + 255) / 256, 27), 256>>>(nbr3, N);

    const int mblk = (N + 127) / 128;
    auto dsm = [](int NT) { return 4 * 10240 + 4 * NT * 80; };

    cudaFuncSetAttribute(tmma<1, 324, 352, 128>,
                         cudaFuncAttributeMaxDynamicSharedMemorySize, dsm(128));
    cudaFuncSetAttribute(tap_mma<256, 256, 96>,
                         cudaFuncAttributeMaxDynamicSharedMemorySize, dsm(96));
    cudaFuncSetAttribute(tap_mma<128, 128, 64>,
                         cudaFuncAttributeMaxDynamicSharedMemorySize, dsm(64));
    cudaFuncSetAttribute(tap_mma<256, 256, 128>,
                         cudaFuncAttributeMaxDynamicSharedMemorySize, dsm(128));

    // corr1 = relu(corrf @ Wc1 + bc1)  (dense identity)
    tmma<1, 324, 352, 128><<<dim3(mblk, 2), 256, dsm(128)>>>(
        corrf, 324, c1h, c1l, 256, bc1, p_corr1, 256, 0, 256, N);

    // f1 = relu(flow_conv)
    flow_conv<<<(N + 63) / 64, 256>>>(flow, nbr7, Wf1, bf1, p_f1, N);

    // cat = bias, then rulebook accumulate, then relu
    init_bias<<<((long)N * 192 + 255) / 256, 256>>>(p_cat, 256, 0, bc2, 192, N);
    init_bias<<<((long)N * 64 + 255) / 256, 256>>>(p_cat, 256, 192, bf2, 64, N);

    tap_mma<256, 256, 96><<<dim3(mblk, 2, 27), 256, dsm(96)>>>(
        p_corr1, 256, c2h, c2l, 192, p_cat, 256, 0, 192);
    tap_mma<128, 128, 64><<<dim3(mblk, 1, 27), 256, dsm(64)>>>(
        p_f1, 128, f2h, f2l, 64, p_cat, 256, 192, 64);

    relu_region<<<((long)N * 256 + 255) / 256, 256>>>(p_cat, 256, 0, 256, N);

    // out[:,0:120] = relu(rulebook conv over cat)
    init_bias<<<((long)N * 120 + 255) / 256, 256>>>(out, 128, 0, bcat, 120, N);
    tap_mma<256, 256, 128><<<dim3(mblk, 1, 27), 256, dsm(128)>>>(
        p_cat, 256, cth, ctl, 128, out, 128, 0, 120);
    relu_region<<<((long)N * 120 + 255) / 256, 256>>>(out, 128, 0, 120, N);

    tail_copy<<<(N * 8 + 255) / 256, 256>>>(extr, flow, out, N);
}

// round 10
// speedup vs baseline: 5.6856x; 1.0608x over previous
#include <cuda_runtime.h>
#include <cuda_bf16.h>
#include <cstdint>

// ===========================================================================
// SparseMotionEncoder — round 7: persistent rulebook HMMA + scheduling fixes.
//  - device-built (tap, mtile) work schedule; persistent tap GEMM blocks
//  - __launch_bounds__(256,2) to pin 2 CTAs/SM
//  - ReLU fused into final conv's gather
//  - flow_conv: 512 threads, 4-row warp granularity tap skipping
// Numerics: bf16x3 split (Ah*Bh + Al*Bh + Ah*Bl), fp32 accum. rel_err ~2e-6.
// ===========================================================================

#define NVOX 50000

__device__ float g_corr1[NVOX * 256];
__device__ float g_f1[NVOX * 128];
__device__ float g_cat[NVOX * 256];

__device__ int  g_cnt3[27];
__device__ int2 g_list3[27 * NVOX];     // (in_idx, out_idx) per tap
__device__ int  g_nitems;
__device__ int  g_items[10560];         // packed: tap | (mtile << 5)

// Transposed, split weights: [KK][COUTPAD][CINPAD] bf16, zero padded.
__device__ __nv_bfloat16 gW_c1_hi[1 * 256 * 352], gW_c1_lo[1 * 256 * 352];
__device__ __nv_bfloat16 gW_c2_hi[27 * 192 * 256], gW_c2_lo[27 * 192 * 256];
__device__ __nv_bfloat16 gW_f2_hi[27 * 64 * 128],  gW_f2_lo[27 * 64 * 128];
__device__ __nv_bfloat16 gW_ct_hi[27 * 128 * 256], gW_ct_lo[27 * 128 * 256];

__device__ __forceinline__ uint32_t pkbf(float a, float b) {
    __nv_bfloat162 t = __floats2bfloat162_rn(a, b);
    return *reinterpret_cast<uint32_t*>(&t);
}
__device__ __forceinline__ void mma16816(float* c, const uint32_t* a,
                                         const uint32_t* b) {
    asm volatile(
        "mma.sync.aligned.m16n8k16.row.col.f32.bf16.bf16.f32 "
        "{%0,%1,%2,%3}, {%4,%5,%6,%7}, {%8,%9}, {%0,%1,%2,%3};"
        : "+f"(c[0]), "+f"(c[1]), "+f"(c[2]), "+f"(c[3])
        : "r"(a[0]), "r"(a[1]), "r"(a[2]), "r"(a[3]), "r"(b[0]), "r"(b[1]));
}
__device__ __forceinline__ void ldsm4(uint32_t* r, uint32_t addr) {
    asm volatile(
        "ldmatrix.sync.aligned.m8n8.x4.shared.b16 {%0,%1,%2,%3}, [%4];"
        : "=r"(r[0]), "=r"(r[1]), "=r"(r[2]), "=r"(r[3]) : "r"(addr));
}
__device__ __forceinline__ void cpasync16(uint32_t dst, const void* src) {
    asm volatile("cp.async.cg.shared.global [%0], [%1], 16;" :: "r"(dst), "l"(src));
}
#define CP_COMMIT() asm volatile("cp.async.commit_group;" ::: "memory")
#define CP_WAIT0()  asm volatile("cp.async.wait_group 0;" ::: "memory")

// ---------------------------------------------------------------------------
template <int KK, int CIN, int COUT, int CINPAD, int COUTPAD>
__global__ void prep_w(const float* __restrict__ W,
                       __nv_bfloat16* __restrict__ hi,
                       __nv_bfloat16* __restrict__ lo)
{
    long tid = (long)blockIdx.x * blockDim.x + threadIdx.x;
    const long total = (long)KK * COUTPAD * CINPAD;
    if (tid >= total) return;
    int c = tid % CINPAD;
    long r = tid / CINPAD;
    int n = r % COUTPAD;
    int k = r / COUTPAD;
    float x = (c < CIN && n < COUT) ? W[((size_t)k * CIN + c) * COUT + n] : 0.f;
    __nv_bfloat16 h = __float2bfloat16(x);
    hi[tid] = h;
    lo[tid] = __float2bfloat16(x - __bfloat162float(h));
}

// ---------------------------------------------------------------------------
__global__ void zero_cnt()
{
    if (threadIdx.x < 27) g_cnt3[threadIdx.x] = 0;
    if (threadIdx.x == 31) g_nitems = 0;
}

__global__ void build_list(const int* __restrict__ nbr, int N)
{
    const int k = blockIdx.y;
    const int n = blockIdx.x * 256 + threadIdx.x;
    const int lane = threadIdx.x & 31;
    int idx = -1;
    if (n < N) idx = nbr[(size_t)k * N + n];
    const bool v = idx >= 0;
    unsigned m = __ballot_sync(0xffffffffu, v);
    if (!m) return;
    int leader = __ffs(m) - 1;
    int base = 0;
    if (lane == leader) base = atomicAdd(&g_cnt3[k], __popc(m));
    base = __shfl_sync(0xffffffffu, base, leader);
    if (v) {
        int pos = base + __popc(m & ((1u << lane) - 1u));
        g_list3[(size_t)k * NVOX + pos] = make_int2(idx, n);
    }
}

__global__ void sched()
{
    int k = threadIdx.x;
    if (k < 27) {
        int tiles = (g_cnt3[k] + 127) >> 7;
        int base = atomicAdd(&g_nitems, tiles);
        for (int i = 0; i < tiles; ++i)
            g_items[base + i] = k | (i << 5);
    }
}

// ---------------------------------------------------------------------------
__global__ void init_bias(float* __restrict__ out, int ostride, int ocol,
                          const float* __restrict__ bias, int COUT, int N)
{
    long i = (long)blockIdx.x * blockDim.x + threadIdx.x;
    if (i >= (long)N * COUT) return;
    int r = i / COUT, c = i % COUT;
    out[(size_t)r * ostride + ocol + c] = bias[c];
}

__global__ void relu_region(float* __restrict__ p, int stride, int ocol,
                            int COUT, int N)
{
    long i = (long)blockIdx.x * blockDim.x + threadIdx.x;
    if (i >= (long)N * COUT) return;
    int r = i / COUT, c = i % COUT;
    float* q = p + (size_t)r * stride + ocol + c;
    *q = fmaxf(*q, 0.f);
}

// ---------------------------------------------------------------------------
// Dense pipelined HMMA gather-GEMM (identity rows) — c1 only.
// ---------------------------------------------------------------------------
template <int KK, int CIN, int CINPAD, int NT>
__global__ void __launch_bounds__(256, 2)
tmma(const float* __restrict__ feat, int fstride,
     const __nv_bfloat16* __restrict__ Whi, const __nv_bfloat16* __restrict__ Wlo,
     int COUTPAD, const float* __restrict__ bias, float* __restrict__ out,
     int ostride, int ocol, int COUT, int N)
{
    constexpr bool TAIL = (CIN % 32) != 0;
    constexpr int CH = CINPAD / 32;
    constexpr int ITERS = KK * CH;
    constexpr int WN = NT / 2;
    constexpr int J  = NT / 16;
    constexpr int JP = J / 2;
    constexpr int BQ = (NT * 8) / 256;
    constexpr uint32_t AB = 10240;
    constexpr uint32_t BB = NT * 80;

    extern __shared__ char dyn[];
    const uint32_t sb = (uint32_t)__cvta_generic_to_shared(dyn);

    const int t = threadIdx.x, lane = t & 31, w = t >> 5;
    const int wm = w >> 1, wn = w & 1;
    const int g = lane >> 2, tg = lane & 3;
    const int row0 = blockIdx.x * 128;
    const int n0 = blockIdx.y * NT;

    float acc[2][J][4];
#pragma unroll
    for (int i = 0; i < 2; ++i)
#pragma unroll
        for (int j = 0; j < J; ++j)
#pragma unroll
            for (int q = 0; q < 4; ++q) acc[i][j][q] = 0.f;

    const int gr = t >> 1;
    const int gcb = (t & 1) * 16;
    const int grow = row0 + gr;

    float4 va[4];

    auto gatherA = [&](int it) {
        const int cc = it % CH;
        const float* frow = (grow < N) ? feat + (size_t)grow * fstride : nullptr;
        const int c0 = cc * 32;
#pragma unroll
        for (int i = 0; i < 4; ++i) {
            const int gcol = c0 + gcb + i * 4;
            float4 v = make_float4(0.f, 0.f, 0.f, 0.f);
            if (frow) {
                if (!TAIL || gcol + 3 < CIN) {
                    v = *reinterpret_cast<const float4*>(frow + gcol);
                } else {
                    float tmp[4] = {0.f, 0.f, 0.f, 0.f};
#pragma unroll
                    for (int jj = 0; jj < 4; ++jj)
                        if (gcol + jj < CIN) tmp[jj] = frow[gcol + jj];
                    v = make_float4(tmp[0], tmp[1], tmp[2], tmp[3]);
                }
            }
            va[i] = v;
        }
    };

    auto storeA = [&](int stage) {
        char* base_h = dyn + (stage * 2 + 0) * AB;
        char* base_l = dyn + (stage * 2 + 1) * AB;
        const int roff = gr * 80;
#pragma unroll
        for (int i = 0; i < 4; ++i) {
            float4 v = va[i];
            float hx = __bfloat162float(__float2bfloat16(v.x));
            float hy = __bfloat162float(__float2bfloat16(v.y));
            float hz = __bfloat162float(__float2bfloat16(v.z));
            float hw = __bfloat162float(__float2bfloat16(v.w));
            uint2 uh = make_uint2(pkbf(hx, hy), pkbf(hz, hw));
            uint2 ul = make_uint2(pkbf(v.x - hx, v.y - hy),
                                  pkbf(v.z - hz, v.w - hw));
            const int boff = roff + (gcb + i * 4) * 2;
            *reinterpret_cast<uint2*>(base_h + boff) = uh;
            *reinterpret_cast<uint2*>(base_l + boff) = ul;
        }
    };

    auto issueB = [&](int it, int stage) {
        const int k = it / CH, cc = it % CH;
        const size_t base = ((size_t)k * COUTPAD + n0) * CINPAD + cc * 32;
#pragma unroll
        for (int q = 0; q < BQ; ++q) {
            const int e = t + q * 256;
            const int plane = e / (NT * 4);
            const int re = e - plane * (NT * 4);
            const int row = re >> 2, seg = re & 3;
            const __nv_bfloat16* src =
                (plane ? Wlo : Whi) + base + (size_t)row * CINPAD + seg * 8;
            const uint32_t dst =
                sb + 4 * AB + (uint32_t)(stage * 2 + plane) * BB + row * 80 + seg * 16;
            cpasync16(dst, src);
        }
    };

    gatherA(0);
    issueB(0, 0);
    CP_COMMIT();
    storeA(0);
    CP_WAIT0();
    __syncthreads();

    const int local = lane & 7, grp = lane >> 3;
    const int arow = (grp & 1) * 8 + local;
    const int abyt = (grp >> 1) * 16;
    const int nloc = (grp >> 1) * 8 + local;
    const int bbyt = (grp & 1) * 16;

#pragma unroll 1
    for (int it = 0; it < ITERS; ++it) {
        const int cur = it & 1, nxt = cur ^ 1;
        const bool more = (it + 1 < ITERS);
        if (more) {
            gatherA(it + 1);
            issueB(it + 1, nxt);
            CP_COMMIT();
        }
        const uint32_t aH = sb + (uint32_t)(cur * 2 + 0) * AB;
        const uint32_t aL = sb + (uint32_t)(cur * 2 + 1) * AB;
        const uint32_t bH = sb + 4 * AB + (uint32_t)(cur * 2 + 0) * BB;
        const uint32_t bL = sb + 4 * AB + (uint32_t)(cur * 2 + 1) * BB;
#pragma unroll
        for (int ks = 0; ks < 2; ++ks) {
            uint32_t Ah[2][4], Al[2][4];
#pragma unroll
            for (int i = 0; i < 2; ++i) {
                const uint32_t ao =
                    (uint32_t)((wm * 32 + i * 16 + arow) * 80 + ks * 32 + abyt);
                ldsm4(Ah[i], aH + ao);
                ldsm4(Al[i], aL + ao);
            }
#pragma unroll
            for (int jp = 0; jp < JP; ++jp) {
                const uint32_t bo =
                    (uint32_t)((wn * WN + jp * 16 + nloc) * 80 + ks * 32 + bbyt);
                uint32_t Bh[4], Bl[4];
                ldsm4(Bh, bH + bo);
                ldsm4(Bl, bL + bo);
#pragma unroll
                for (int i = 0; i < 2; ++i) {
                    mma16816(acc[i][2 * jp],     Ah[i], Bh);
                    mma16816(acc[i][2 * jp],     Al[i], Bh);
                    mma16816(acc[i][2 * jp],     Ah[i], Bl);
                    mma16816(acc[i][2 * jp + 1], Ah[i], Bh + 2);
                    mma16816(acc[i][2 * jp + 1], Al[i], Bh + 2);
                    mma16816(acc[i][2 * jp + 1], Ah[i], Bl + 2);
                }
            }
        }
        if (more) {
            storeA(nxt);
            CP_WAIT0();
        }
        __syncthreads();
    }

#pragma unroll
    for (int j = 0; j < J; ++j) {
        const int col = n0 + wn * WN + j * 8 + tg * 2;
        if (col >= COUT) continue;
        const float2 bv = *reinterpret_cast<const float2*>(bias + col);
#pragma unroll
        for (int i = 0; i < 2; ++i) {
            const int r1 = row0 + wm * 32 + i * 16 + g;
            if (r1 < N) {
                float2 o = make_float2(fmaxf(acc[i][j][0] + bv.x, 0.f),
                                       fmaxf(acc[i][j][1] + bv.y, 0.f));
                *reinterpret_cast<float2*>(out + (size_t)r1 * ostride + ocol + col) = o;
            }
            const int r2 = r1 + 8;
            if (r2 < N) {
                float2 o = make_float2(fmaxf(acc[i][j][2] + bv.x, 0.f),
                                       fmaxf(acc[i][j][3] + bv.y, 0.f));
                *reinterpret_cast<float2*>(out + (size_t)r2 * ostride + ocol + col) = o;
            }
        }
    }
}

// ---------------------------------------------------------------------------
// Persistent per-tap rulebook HMMA GEMM. Grid-stride over device-built work
// items (tap, mtile) x NYT n-tiles. Accumulates via atomicAdd.
// RELUIN: apply relu to gathered input (fuses producer's relu).
// ---------------------------------------------------------------------------
template <int CIN, int CINPAD, int NT, int NYT, bool RELUIN>
__global__ void __launch_bounds__(256, 2)
tap_mma_p(const float* __restrict__ feat, int fstride,
          const __nv_bfloat16* __restrict__ Whi, const __nv_bfloat16* __restrict__ Wlo,
          int COUTPAD, float* __restrict__ out, int ostride, int ocol, int COUT)
{
    constexpr int CH = CINPAD / 32;
    constexpr int WN = NT / 2;
    constexpr int J  = NT / 16;
    constexpr int JP = J / 2;
    constexpr int BQ = (NT * 8) / 256;
    constexpr uint32_t AB = 10240;
    constexpr uint32_t BB = NT * 80;

    __shared__ int sIn[128], sOut[128];
    extern __shared__ char dyn[];
    const uint32_t sb = (uint32_t)__cvta_generic_to_shared(dyn);

    const int t = threadIdx.x, lane = t & 31, w = t >> 5;
    const int wm = w >> 1, wn = w & 1;
    const int g = lane >> 2, tg = lane & 3;
    const int gr = t >> 1;
    const int gcb = (t & 1) * 16;
    const int local = lane & 7, grp = lane >> 3;
    const int arow = (grp & 1) * 8 + local;
    const int abyt = (grp >> 1) * 16;
    const int nloc = (grp >> 1) * 8 + local;
    const int bbyt = (grp & 1) * 16;

    const int nwork = g_nitems * NYT;

    for (int wk = blockIdx.x; wk < nwork; wk += gridDim.x) {
        const int item = (NYT == 1) ? wk : (wk >> 1);
        const int y    = (NYT == 1) ? 0  : (wk & 1);
        const int packed = g_items[item];
        const int tap = packed & 31;
        const int m0 = (packed >> 5) << 7;
        const int cn = g_cnt3[tap];
        const int n0 = y * NT;

        __syncthreads();   // previous item's epilogue reads of sIn/sOut done
        if (t < 128) {
            const int m = m0 + t;
            if (m < cn) {
                int2 p = g_list3[(size_t)tap * NVOX + m];
                sIn[t] = p.x;
                sOut[t] = p.y;
            } else {
                sIn[t] = -1;
                sOut[t] = -1;
            }
        }
        __syncthreads();

        float acc[2][J][4];
#pragma unroll
        for (int i = 0; i < 2; ++i)
#pragma unroll
            for (int j = 0; j < J; ++j)
#pragma unroll
                for (int q = 0; q < 4; ++q) acc[i][j][q] = 0.f;

        const int gin = sIn[gr];
        const float* frow = (gin >= 0) ? feat + (size_t)gin * fstride : nullptr;

        float4 va[4];
        auto gatherA = [&](int it) {
            const int c0 = it * 32;
#pragma unroll
            for (int i = 0; i < 4; ++i) {
                float4 v = make_float4(0.f, 0.f, 0.f, 0.f);
                if (frow) {
                    v = *reinterpret_cast<const float4*>(frow + c0 + gcb + i * 4);
                    if (RELUIN) {
                        v.x = fmaxf(v.x, 0.f);
                        v.y = fmaxf(v.y, 0.f);
                        v.z = fmaxf(v.z, 0.f);
                        v.w = fmaxf(v.w, 0.f);
                    }
                }
                va[i] = v;
            }
        };
        auto storeA = [&](int stage) {
            char* base_h = dyn + (stage * 2 + 0) * AB;
            char* base_l = dyn + (stage * 2 + 1) * AB;
            const int roff = gr * 80;
#pragma unroll
            for (int i = 0; i < 4; ++i) {
                float4 v = va[i];
                float hx = __bfloat162float(__float2bfloat16(v.x));
                float hy = __bfloat162float(__float2bfloat16(v.y));
                float hz = __bfloat162float(__float2bfloat16(v.z));
                float hw = __bfloat162float(__float2bfloat16(v.w));
                uint2 uh = make_uint2(pkbf(hx, hy), pkbf(hz, hw));
                uint2 ul = make_uint2(pkbf(v.x - hx, v.y - hy),
                                      pkbf(v.z - hz, v.w - hw));
                const int boff = roff + (gcb + i * 4) * 2;
                *reinterpret_cast<uint2*>(base_h + boff) = uh;
                *reinterpret_cast<uint2*>(base_l + boff) = ul;
            }
        };
        auto issueB = [&](int it, int stage) {
            const size_t base = ((size_t)tap * COUTPAD + n0) * CINPAD + it * 32;
#pragma unroll
            for (int q = 0; q < BQ; ++q) {
                const int e = t + q * 256;
                const int plane = e / (NT * 4);
                const int re = e - plane * (NT * 4);
                const int row = re >> 2, seg = re & 3;
                const __nv_bfloat16* src =
                    (plane ? Wlo : Whi) + base + (size_t)row * CINPAD + seg * 8;
                const uint32_t dst =
                    sb + 4 * AB + (uint32_t)(stage * 2 + plane) * BB + row * 80 + seg * 16;
                cpasync16(dst, src);
            }
        };

        gatherA(0);
        issueB(0, 0);
        CP_COMMIT();
        storeA(0);
        CP_WAIT0();
        __syncthreads();

#pragma unroll 1
        for (int it = 0; it < CH; ++it) {
            const int cur = it & 1, nxt = cur ^ 1;
            const bool more = (it + 1 < CH);
            if (more) {
                gatherA(it + 1);
                issueB(it + 1, nxt);
                CP_COMMIT();
            }
            const uint32_t aH = sb + (uint32_t)(cur * 2 + 0) * AB;
            const uint32_t aL = sb + (uint32_t)(cur * 2 + 1) * AB;
            const uint32_t bH = sb + 4 * AB + (uint32_t)(cur * 2 + 0) * BB;
            const uint32_t bL = sb + 4 * AB + (uint32_t)(cur * 2 + 1) * BB;
#pragma unroll
            for (int ks = 0; ks < 2; ++ks) {
                uint32_t Ah[2][4], Al[2][4];
#pragma unroll
                for (int i = 0; i < 2; ++i) {
                    const uint32_t ao =
                        (uint32_t)((wm * 32 + i * 16 + arow) * 80 + ks * 32 + abyt);
                    ldsm4(Ah[i], aH + ao);
                    ldsm4(Al[i], aL + ao);
                }
#pragma unroll
                for (int jp = 0; jp < JP; ++jp) {
                    const uint32_t bo =
                        (uint32_t)((wn * WN + jp * 16 + nloc) * 80 + ks * 32 + bbyt);
                    uint32_t Bh[4], Bl[4];
                    ldsm4(Bh, bH + bo);
                    ldsm4(Bl, bL + bo);
#pragma unroll
                    for (int i = 0; i < 2; ++i) {
                        mma16816(acc[i][2 * jp],     Ah[i], Bh);
                        mma16816(acc[i][2 * jp],     Al[i], Bh);
                        mma16816(acc[i][2 * jp],     Ah[i], Bl);
                        mma16816(acc[i][2 * jp + 1], Ah[i], Bh + 2);
                        mma16816(acc[i][2 * jp + 1], Al[i], Bh + 2);
                        mma16816(acc[i][2 * jp + 1], Ah[i], Bl + 2);
                    }
                }
            }
            if (more) {
                storeA(nxt);
                CP_WAIT0();
            }
            __syncthreads();
        }

        // ---- epilogue: atomic accumulate ----
#pragma unroll
        for (int j = 0; j < J; ++j) {
            const int col = n0 + wn * WN + j * 8 + tg * 2;
            if (col >= COUT) continue;
#pragma unroll
            for (int i = 0; i < 2; ++i) {
                const int lr1 = wm * 32 + i * 16 + g;
                const int ro1 = sOut[lr1];
                if (ro1 >= 0) {
                    float* p = out + (size_t)ro1 * ostride + ocol + col;
                    atomicAdd(p, acc[i][j][0]);
                    atomicAdd(p + 1, acc[i][j][1]);
                }
                const int ro2 = sOut[lr1 + 8];
                if (ro2 >= 0) {
                    float* p = out + (size_t)ro2 * ostride + ocol + col;
                    atomicAdd(p, acc[i][j][2]);
                    atomicAdd(p + 1, acc[i][j][3]);
                }
            }
        }
    }
}

// ---------------------------------------------------------------------------
// Flow conv (K=343, Cin=2, Cout=128): 512 threads, 16 warps x 4 rows,
// double-buffered, per-warp (4-row) tap skipping.
// ---------------------------------------------------------------------------
__global__ void __launch_bounds__(512)
flow_conv(const float* __restrict__ flow, const int* __restrict__ nbr7,
          const float* __restrict__ W, const float* __restrict__ bias,
          float* __restrict__ out, int N)
{
    constexpr int KK = 343, BM = 64;
    __shared__ float sF[2][BM * 2];
    __shared__ float sW[2][256];
    __shared__ unsigned char sV[2][BM];

    const int t = threadIdx.x;
    const int warp = t >> 5, lane = t & 31;
    const int row0 = blockIdx.x * BM;

    float acc[4][4];
#pragma unroll
    for (int i = 0; i < 4; ++i)
#pragma unroll
        for (int j = 0; j < 4; ++j) acc[i][j] = 0.f;

    auto load_stage = [&](int k, int buf) {
        if (t < BM) {
            int r = row0 + t;
            int idx = (r < N) ? nbr7[(size_t)k * N + r] : -1;
            float2 v = make_float2(0.f, 0.f);
            if (idx >= 0) v = *reinterpret_cast<const float2*>(&flow[(size_t)idx * 2]);
            sF[buf][t * 2] = v.x;
            sF[buf][t * 2 + 1] = v.y;
            sV[buf][t] = (idx >= 0);
        }
        if (t < 256) sW[buf][t] = W[(size_t)k * 256 + t];
    };

    load_stage(0, 0);
    for (int k = 0; k < KK; ++k) {
        __syncthreads();
        if (k + 1 < KK) load_stage(k + 1, (k + 1) & 1);
        const int buf = k & 1;
        const bool myv = (lane < 4) && (sV[buf][warp * 4 + lane] != 0);
        if (__ballot_sync(0xffffffffu, myv)) {
            const float4 w0 = *reinterpret_cast<const float4*>(&sW[buf][lane * 4]);
            const float4 w1 = *reinterpret_cast<const float4*>(&sW[buf][128 + lane * 4]);
#pragma unroll
            for (int i = 0; i < 4; ++i) {
                const float f0 = sF[buf][(warp * 4 + i) * 2];
                const float f1 = sF[buf][(warp * 4 + i) * 2 + 1];
                acc[i][0] = fmaf(f0, w0.x, fmaf(f1, w1.x, acc[i][0]));
                acc[i][1] = fmaf(f0, w0.y, fmaf(f1, w1.y, acc[i][1]));
                acc[i][2] = fmaf(f0, w0.z, fmaf(f1, w1.z, acc[i][2]));
                acc[i][3] = fmaf(f0, w0.w, fmaf(f1, w1.w, acc[i][3]));
            }
        }
    }

    const float4 bv = *reinterpret_cast<const float4*>(&bias[lane * 4]);
#pragma unroll
    for (int i = 0; i < 4; ++i) {
        const int r = row0 + warp * 4 + i;
        if (r >= N) continue;
        float4 o;
        o.x = fmaxf(acc[i][0] + bv.x, 0.f);
        o.y = fmaxf(acc[i][1] + bv.y, 0.f);
        o.z = fmaxf(acc[i][2] + bv.z, 0.f);
        o.w = fmaxf(acc[i][3] + bv.w, 0.f);
        *reinterpret_cast<float4*>(out + (size_t)r * 128 + lane * 4) = o;
    }
}

__global__ void tail_copy(const float* __restrict__ ext,
                          const float* __restrict__ flow,
                          float* __restrict__ out, int N)
{
    int i = blockIdx.x * blockDim.x + threadIdx.x;
    if (i >= N * 8) return;
    int r = i >> 3, c = i & 7;
    float v = (c < 2) ? flow[(size_t)r * 2 + c] : ext[(size_t)r * 6 + (c - 2)];
    out[(size_t)r * 128 + 120 + c] = v;
}

// ---------------------------------------------------------------------------
extern "C" void kernel_launch(void* const* d_in, const int* in_sizes, int n_in,
                              void* d_out, int out_size)
{
    const float* extr  = (const float*)d_in[0];
    const float* flow  = (const float*)d_in[1];
    const float* corrf = (const float*)d_in[2];
    const int*   nbr3  = (const int*)  d_in[3];
    const int*   nbr7  = (const int*)  d_in[4];
    const float* Wc1   = (const float*)d_in[5];
    const float* bc1   = (const float*)d_in[6];
    const float* Wc2   = (const float*)d_in[7];
    const float* bc2   = (const float*)d_in[8];
    const float* Wf1   = (const float*)d_in[9];
    const float* bf1   = (const float*)d_in[10];
    const float* Wf2   = (const float*)d_in[11];
    const float* bf2   = (const float*)d_in[12];
    const float* Wcat  = (const float*)d_in[13];
    const float* bcat  = (const float*)d_in[14];
    float* out = (float*)d_out;

    const int N = in_sizes[0] / 6;

    float *p_corr1, *p_f1, *p_cat;
    cudaGetSymbolAddress((void**)&p_corr1, g_corr1);
    cudaGetSymbolAddress((void**)&p_f1,    g_f1);
    cudaGetSymbolAddress((void**)&p_cat,   g_cat);
    __nv_bfloat16 *c1h, *c1l, *c2h, *c2l, *f2h, *f2l, *cth, *ctl;
    cudaGetSymbolAddress((void**)&c1h, gW_c1_hi);
    cudaGetSymbolAddress((void**)&c1l, gW_c1_lo);
    cudaGetSymbolAddress((void**)&c2h, gW_c2_hi);
    cudaGetSymbolAddress((void**)&c2l, gW_c2_lo);
    cudaGetSymbolAddress((void**)&f2h, gW_f2_hi);
    cudaGetSymbolAddress((void**)&f2l, gW_f2_lo);
    cudaGetSymbolAddress((void**)&cth, gW_ct_hi);
    cudaGetSymbolAddress((void**)&ctl, gW_ct_lo);

    int nsm = 148;
    cudaDeviceGetAttribute(&nsm, cudaDevAttrMultiProcessorCount, 0);
    const int pgrid = nsm * 2;

    // ---- weight prep + rulebook build + schedule ----
    prep_w<1, 324, 256, 352, 256><<<(1 * 256 * 352 + 255) / 256, 256>>>(Wc1, c1h, c1l);
    prep_w<27, 256, 192, 256, 192><<<(27 * 192 * 256 + 255) / 256, 256>>>(Wc2, c2h, c2l);
    prep_w<27, 128, 64, 128, 64><<<(27 * 64 * 128 + 255) / 256, 256>>>(Wf2, f2h, f2l);
    prep_w<27, 256, 120, 256, 128><<<(27 * 128 * 256 + 255) / 256, 256>>>(Wcat, cth, ctl);
    zero_cnt<<<1, 32>>>();
    build_list<<<dim3((N + 255) / 256, 27), 256>>>(nbr3, N);
    sched<<<1, 32>>>();

    const int mblk = (N + 127) / 128;
    auto dsm = [](int NT) { return 4 * 10240 + 4 * NT * 80; };

    cudaFuncSetAttribute(tmma<1, 324, 352, 128>,
                         cudaFuncAttributeMaxDynamicSharedMemorySize, dsm(128));
    cudaFuncSetAttribute(tap_mma_p<256, 256, 96, 2, false>,
                         cudaFuncAttributeMaxDynamicSharedMemorySize, dsm(96));
    cudaFuncSetAttribute(tap_mma_p<128, 128, 64, 1, false>,
                         cudaFuncAttributeMaxDynamicSharedMemorySize, dsm(64));
    cudaFuncSetAttribute(tap_mma_p<256, 256, 128, 1, true>,
                         cudaFuncAttributeMaxDynamicSharedMemorySize, dsm(128));

    // corr1 = relu(corrf @ Wc1 + bc1)  (dense identity)
    tmma<1, 324, 352, 128><<<dim3(mblk, 2), 256, dsm(128)>>>(
        corrf, 324, c1h, c1l, 256, bc1, p_corr1, 256, 0, 256, N);

    // f1 = relu(flow_conv)
    flow_conv<<<(N + 63) / 64, 512>>>(flow, nbr7, Wf1, bf1, p_f1, N);

    // cat = bias, then rulebook accumulate (relu fused into consumer)
    init_bias<<<((long)N * 192 + 255) / 256, 256>>>(p_cat, 256, 0, bc2, 192, N);
    init_bias<<<((long)N * 64 + 255) / 256, 256>>>(p_cat, 256, 192, bf2, 64, N);

    tap_mma_p<256, 256, 96, 2, false><<<pgrid, 256, dsm(96)>>>(
        p_corr1, 256, c2h, c2l, 192, p_cat, 256, 0, 192);
    tap_mma_p<128, 128, 64, 1, false><<<pgrid, 256, dsm(64)>>>(
        p_f1, 128, f2h, f2l, 64, p_cat, 256, 192, 64);

    // out[:,0:120]: bias init, rulebook conv over relu(cat), final relu
    init_bias<<<((long)N * 120 + 255) / 256, 256>>>(out, 128, 0, bcat, 120, N);
    tap_mma_p<256, 256, 128, 1, true><<<pgrid, 256, dsm(128)>>>(
        p_cat, 256, cth, ctl, 128, out, 128, 0, 120);
    relu_region<<<((long)N * 120 + 255) / 256, 256>>>(out, 128, 0, 120, N);

    tail_copy<<<(N * 8 + 255) / 256, 256>>>(extr, flow, out, N);
}

// round 12
// speedup vs baseline: 5.8152x; 1.0228x over previous
#include <cuda_runtime.h>
#include <cuda_bf16.h>
#include <cstdint>

// ===========================================================================
// SparseMotionEncoder — round 11: vectorized atomic epilogue (red.v4.f32).
//  - rulebook HMMA bf16x3 GEMMs (persistent), atomic accumulate
//  - NEW: epilogue stages acc tile through smem, issues red.global.add.v4.f32
//         (4x fewer atomic instructions; fully coalesced 16B reductions)
//  - merged cat bias init; relu fused into final conv's gather
// Numerics: bf16x3 split (Ah*Bh + Al*Bh + Ah*Bl), fp32 accum. rel_err ~2e-6.
// ===========================================================================

#define NVOX 50000

__device__ float g_corr1[NVOX * 256];
__device__ float g_f1[NVOX * 128];
__device__ float g_cat[NVOX * 256];

__device__ int  g_cnt3[27];
__device__ int2 g_list3[27 * NVOX];     // (in_idx, out_idx) per tap
__device__ int  g_nitems;
__device__ int  g_items[10560];         // packed: tap | (mtile << 5)

// Transposed, split weights: [KK][COUTPAD][CINPAD] bf16, zero padded.
__device__ __nv_bfloat16 gW_c1_hi[1 * 256 * 352], gW_c1_lo[1 * 256 * 352];
__device__ __nv_bfloat16 gW_c2_hi[27 * 192 * 256], gW_c2_lo[27 * 192 * 256];
__device__ __nv_bfloat16 gW_f2_hi[27 * 64 * 128],  gW_f2_lo[27 * 64 * 128];
__device__ __nv_bfloat16 gW_ct_hi[27 * 128 * 256], gW_ct_lo[27 * 128 * 256];

__device__ __forceinline__ uint32_t pkbf(float a, float b) {
    __nv_bfloat162 t = __floats2bfloat162_rn(a, b);
    return *reinterpret_cast<uint32_t*>(&t);
}
__device__ __forceinline__ void mma16816(float* c, const uint32_t* a,
                                         const uint32_t* b) {
    asm volatile(
        "mma.sync.aligned.m16n8k16.row.col.f32.bf16.bf16.f32 "
        "{%0,%1,%2,%3}, {%4,%5,%6,%7}, {%8,%9}, {%0,%1,%2,%3};"
        : "+f"(c[0]), "+f"(c[1]), "+f"(c[2]), "+f"(c[3])
        : "r"(a[0]), "r"(a[1]), "r"(a[2]), "r"(a[3]), "r"(b[0]), "r"(b[1]));
}
__device__ __forceinline__ void ldsm4(uint32_t* r, uint32_t addr) {
    asm volatile(
        "ldmatrix.sync.aligned.m8n8.x4.shared.b16 {%0,%1,%2,%3}, [%4];"
        : "=r"(r[0]), "=r"(r[1]), "=r"(r[2]), "=r"(r[3]) : "r"(addr));
}
__device__ __forceinline__ void cpasync16(uint32_t dst, const void* src) {
    asm volatile("cp.async.cg.shared.global [%0], [%1], 16;" :: "r"(dst), "l"(src));
}
__device__ __forceinline__ void red4(float* p, float4 v) {
    asm volatile("red.global.add.v4.f32 [%0], {%1,%2,%3,%4};"
                 :: "l"(p), "f"(v.x), "f"(v.y), "f"(v.z), "f"(v.w) : "memory");
}
#define CP_COMMIT() asm volatile("cp.async.commit_group;" ::: "memory")
#define CP_WAIT0()  asm volatile("cp.async.wait_group 0;" ::: "memory")

// ---------------------------------------------------------------------------
template <int KK, int CIN, int COUT, int CINPAD, int COUTPAD>
__global__ void prep_w(const float* __restrict__ W,
                       __nv_bfloat16* __restrict__ hi,
                       __nv_bfloat16* __restrict__ lo)
{
    long tid = (long)blockIdx.x * blockDim.x + threadIdx.x;
    const long total = (long)KK * COUTPAD * CINPAD;
    if (tid >= total) return;
    int c = tid % CINPAD;
    long r = tid / CINPAD;
    int n = r % COUTPAD;
    int k = r / COUTPAD;
    float x = (c < CIN && n < COUT) ? W[((size_t)k * CIN + c) * COUT + n] : 0.f;
    __nv_bfloat16 h = __float2bfloat16(x);
    hi[tid] = h;
    lo[tid] = __float2bfloat16(x - __bfloat162float(h));
}

// ---------------------------------------------------------------------------
__global__ void zero_cnt()
{
    if (threadIdx.x < 27) g_cnt3[threadIdx.x] = 0;
    if (threadIdx.x == 31) g_nitems = 0;
}

__global__ void build_list(const int* __restrict__ nbr, int N)
{
    const int k = blockIdx.y;
    const int n = blockIdx.x * 256 + threadIdx.x;
    const int lane = threadIdx.x & 31;
    int idx = -1;
    if (n < N) idx = nbr[(size_t)k * N + n];
    const bool v = idx >= 0;
    unsigned m = __ballot_sync(0xffffffffu, v);
    if (!m) return;
    int leader = __ffs(m) - 1;
    int base = 0;
    if (lane == leader) base = atomicAdd(&g_cnt3[k], __popc(m));
    base = __shfl_sync(0xffffffffu, base, leader);
    if (v) {
        int pos = base + __popc(m & ((1u << lane) - 1u));
        g_list3[(size_t)k * NVOX + pos] = make_int2(idx, n);
    }
}

__global__ void sched()
{
    int k = threadIdx.x;
    if (k < 27) {
        int tiles = (g_cnt3[k] + 127) >> 7;
        int base = atomicAdd(&g_nitems, tiles);
        for (int i = 0; i < tiles; ++i)
            g_items[base + i] = k | (i << 5);
    }
}

// ---------------------------------------------------------------------------
__global__ void init_cat(float* __restrict__ cat,
                         const float* __restrict__ b0,   // 192
                         const float* __restrict__ b1,   // 64
                         int N)
{
    long i = (long)blockIdx.x * blockDim.x + threadIdx.x;
    if (i >= (long)N * 256) return;
    int c = i & 255;
    cat[i] = (c < 192) ? b0[c] : b1[c - 192];
}

__global__ void init_bias(float* __restrict__ out, int ostride, int ocol,
                          const float* __restrict__ bias, int COUT, int N)
{
    long i = (long)blockIdx.x * blockDim.x + threadIdx.x;
    if (i >= (long)N * COUT) return;
    int r = i / COUT, c = i % COUT;
    out[(size_t)r * ostride + ocol + c] = bias[c];
}

__global__ void relu_region(float* __restrict__ p, int stride, int ocol,
                            int COUT, int N)
{
    long i = (long)blockIdx.x * blockDim.x + threadIdx.x;
    if (i >= (long)N * COUT) return;
    int r = i / COUT, c = i % COUT;
    float* q = p + (size_t)r * stride + ocol + c;
    *q = fmaxf(*q, 0.f);
}

// ---------------------------------------------------------------------------
// Dense pipelined HMMA gather-GEMM (identity rows) — c1 only.
// ---------------------------------------------------------------------------
template <int KK, int CIN, int CINPAD, int NT>
__global__ void __launch_bounds__(256, 2)
tmma(const float* __restrict__ feat, int fstride,
     const __nv_bfloat16* __restrict__ Whi, const __nv_bfloat16* __restrict__ Wlo,
     int COUTPAD, const float* __restrict__ bias, float* __restrict__ out,
     int ostride, int ocol, int COUT, int N)
{
    constexpr bool TAIL = (CIN % 32) != 0;
    constexpr int CH = CINPAD / 32;
    constexpr int ITERS = KK * CH;
    constexpr int WN = NT / 2;
    constexpr int J  = NT / 16;
    constexpr int JP = J / 2;
    constexpr int BQ = (NT * 8) / 256;
    constexpr uint32_t AB = 10240;
    constexpr uint32_t BB = NT * 80;

    extern __shared__ char dyn[];
    const uint32_t sb = (uint32_t)__cvta_generic_to_shared(dyn);

    const int t = threadIdx.x, lane = t & 31, w = t >> 5;
    const int wm = w >> 1, wn = w & 1;
    const int g = lane >> 2, tg = lane & 3;
    const int row0 = blockIdx.x * 128;
    const int n0 = blockIdx.y * NT;

    float acc[2][J][4];
#pragma unroll
    for (int i = 0; i < 2; ++i)
#pragma unroll
        for (int j = 0; j < J; ++j)
#pragma unroll
            for (int q = 0; q < 4; ++q) acc[i][j][q] = 0.f;

    const int gr = t >> 1;
    const int gcb = (t & 1) * 16;
    const int grow = row0 + gr;

    float4 va[4];

    auto gatherA = [&](int it) {
        const int cc = it % CH;
        const float* frow = (grow < N) ? feat + (size_t)grow * fstride : nullptr;
        const int c0 = cc * 32;
#pragma unroll
        for (int i = 0; i < 4; ++i) {
            const int gcol = c0 + gcb + i * 4;
            float4 v = make_float4(0.f, 0.f, 0.f, 0.f);
            if (frow) {
                if (!TAIL || gcol + 3 < CIN) {
                    v = *reinterpret_cast<const float4*>(frow + gcol);
                } else {
                    float tmp[4] = {0.f, 0.f, 0.f, 0.f};
#pragma unroll
                    for (int jj = 0; jj < 4; ++jj)
                        if (gcol + jj < CIN) tmp[jj] = frow[gcol + jj];
                    v = make_float4(tmp[0], tmp[1], tmp[2], tmp[3]);
                }
            }
            va[i] = v;
        }
    };

    auto storeA = [&](int stage) {
        char* base_h = dyn + (stage * 2 + 0) * AB;
        char* base_l = dyn + (stage * 2 + 1) * AB;
        const int roff = gr * 80;
#pragma unroll
        for (int i = 0; i < 4; ++i) {
            float4 v = va[i];
            float hx = __bfloat162float(__float2bfloat16(v.x));
            float hy = __bfloat162float(__float2bfloat16(v.y));
            float hz = __bfloat162float(__float2bfloat16(v.z));
            float hw = __bfloat162float(__float2bfloat16(v.w));
            uint2 uh = make_uint2(pkbf(hx, hy), pkbf(hz, hw));
            uint2 ul = make_uint2(pkbf(v.x - hx, v.y - hy),
                                  pkbf(v.z - hz, v.w - hw));
            const int boff = roff + (gcb + i * 4) * 2;
            *reinterpret_cast<uint2*>(base_h + boff) = uh;
            *reinterpret_cast<uint2*>(base_l + boff) = ul;
        }
    };

    auto issueB = [&](int it, int stage) {
        const int k = it / CH, cc = it % CH;
        const size_t base = ((size_t)k * COUTPAD + n0) * CINPAD + cc * 32;
#pragma unroll
        for (int q = 0; q < BQ; ++q) {
            const int e = t + q * 256;
            const int plane = e / (NT * 4);
            const int re = e - plane * (NT * 4);
            const int row = re >> 2, seg = re & 3;
            const __nv_bfloat16* src =
                (plane ? Wlo : Whi) + base + (size_t)row * CINPAD + seg * 8;
            const uint32_t dst =
                sb + 4 * AB + (uint32_t)(stage * 2 + plane) * BB + row * 80 + seg * 16;
            cpasync16(dst, src);
        }
    };

    gatherA(0);
    issueB(0, 0);
    CP_COMMIT();
    storeA(0);
    CP_WAIT0();
    __syncthreads();

    const int local = lane & 7, grp = lane >> 3;
    const int arow = (grp & 1) * 8 + local;
    const int abyt = (grp >> 1) * 16;
    const int nloc = (grp >> 1) * 8 + local;
    const int bbyt = (grp & 1) * 16;

#pragma unroll 1
    for (int it = 0; it < ITERS; ++it) {
        const int cur = it & 1, nxt = cur ^ 1;
        const bool more = (it + 1 < ITERS);
        if (more) {
            gatherA(it + 1);
            issueB(it + 1, nxt);
            CP_COMMIT();
        }
        const uint32_t aH = sb + (uint32_t)(cur * 2 + 0) * AB;
        const uint32_t aL = sb + (uint32_t)(cur * 2 + 1) * AB;
        const uint32_t bH = sb + 4 * AB + (uint32_t)(cur * 2 + 0) * BB;
        const uint32_t bL = sb + 4 * AB + (uint32_t)(cur * 2 + 1) * BB;
#pragma unroll
        for (int ks = 0; ks < 2; ++ks) {
            uint32_t Ah[2][4], Al[2][4];
#pragma unroll
            for (int i = 0; i < 2; ++i) {
                const uint32_t ao =
                    (uint32_t)((wm * 32 + i * 16 + arow) * 80 + ks * 32 + abyt);
                ldsm4(Ah[i], aH + ao);
                ldsm4(Al[i], aL + ao);
            }
#pragma unroll
            for (int jp = 0; jp < JP; ++jp) {
                const uint32_t bo =
                    (uint32_t)((wn * WN + jp * 16 + nloc) * 80 + ks * 32 + bbyt);
                uint32_t Bh[4], Bl[4];
                ldsm4(Bh, bH + bo);
                ldsm4(Bl, bL + bo);
#pragma unroll
                for (int i = 0; i < 2; ++i) {
                    mma16816(acc[i][2 * jp],     Ah[i], Bh);
                    mma16816(acc[i][2 * jp],     Al[i], Bh);
                    mma16816(acc[i][2 * jp],     Ah[i], Bl);
                    mma16816(acc[i][2 * jp + 1], Ah[i], Bh + 2);
                    mma16816(acc[i][2 * jp + 1], Al[i], Bh + 2);
                    mma16816(acc[i][2 * jp + 1], Ah[i], Bl + 2);
                }
            }
        }
        if (more) {
            storeA(nxt);
            CP_WAIT0();
        }
        __syncthreads();
    }

#pragma unroll
    for (int j = 0; j < J; ++j) {
        const int col = n0 + wn * WN + j * 8 + tg * 2;
        if (col >= COUT) continue;
        const float2 bv = *reinterpret_cast<const float2*>(bias + col);
#pragma unroll
        for (int i = 0; i < 2; ++i) {
            const int r1 = row0 + wm * 32 + i * 16 + g;
            if (r1 < N) {
                float2 o = make_float2(fmaxf(acc[i][j][0] + bv.x, 0.f),
                                       fmaxf(acc[i][j][1] + bv.y, 0.f));
                *reinterpret_cast<float2*>(out + (size_t)r1 * ostride + ocol + col) = o;
            }
            const int r2 = r1 + 8;
            if (r2 < N) {
                float2 o = make_float2(fmaxf(acc[i][j][2] + bv.x, 0.f),
                                       fmaxf(acc[i][j][3] + bv.y, 0.f));
                *reinterpret_cast<float2*>(out + (size_t)r2 * ostride + ocol + col) = o;
            }
        }
    }
}

// ---------------------------------------------------------------------------
// Persistent per-tap rulebook HMMA GEMM. Grid-stride over device-built work
// items (tap, mtile) x NYT n-tiles. Epilogue: stage acc tile in smem, then
// coalesced red.global.add.v4.f32.
// ---------------------------------------------------------------------------
template <int CIN, int CINPAD, int NT, int NYT, bool RELUIN>
__global__ void __launch_bounds__(256, 2)
tap_mma_p(const float* __restrict__ feat, int fstride,
          const __nv_bfloat16* __restrict__ Whi, const __nv_bfloat16* __restrict__ Wlo,
          int COUTPAD, float* __restrict__ out, int ostride, int ocol, int COUT)
{
    constexpr int CH = CINPAD / 32;
    constexpr int WN = NT / 2;
    constexpr int J  = NT / 16;
    constexpr int JP = J / 2;
    constexpr int BQ = (NT * 8) / 256;
    constexpr uint32_t AB = 10240;
    constexpr uint32_t BB = NT * 80;
    constexpr int RSF = NT + 4;          // acc stage row stride (floats)
    constexpr int NQ = NT / 4;

    __shared__ int sIn[128], sOut[128];
    extern __shared__ char dyn[];
    const uint32_t sb = (uint32_t)__cvta_generic_to_shared(dyn);
    float* sAcc = reinterpret_cast<float*>(dyn);

    const int t = threadIdx.x, lane = t & 31, w = t >> 5;
    const int wm = w >> 1, wn = w & 1;
    const int g = lane >> 2, tg = lane & 3;
    const int gr = t >> 1;
    const int gcb = (t & 1) * 16;
    const int local = lane & 7, grp = lane >> 3;
    const int arow = (grp & 1) * 8 + local;
    const int abyt = (grp >> 1) * 16;
    const int nloc = (grp >> 1) * 8 + local;
    const int bbyt = (grp & 1) * 16;

    const int nwork = g_nitems * NYT;

    for (int wk = blockIdx.x; wk < nwork; wk += gridDim.x) {
        const int item = (NYT == 1) ? wk : (wk >> 1);
        const int y    = (NYT == 1) ? 0  : (wk & 1);
        const int packed = g_items[item];
        const int tap = packed & 31;
        const int m0 = (packed >> 5) << 7;
        const int cn = g_cnt3[tap];
        const int n0 = y * NT;

        __syncthreads();   // prior epilogue's smem reads done
        if (t < 128) {
            const int m = m0 + t;
            if (m < cn) {
                int2 p = g_list3[(size_t)tap * NVOX + m];
                sIn[t] = p.x;
                sOut[t] = p.y;
            } else {
                sIn[t] = -1;
                sOut[t] = -1;
            }
        }
        __syncthreads();

        float acc[2][J][4];
#pragma unroll
        for (int i = 0; i < 2; ++i)
#pragma unroll
            for (int j = 0; j < J; ++j)
#pragma unroll
                for (int q = 0; q < 4; ++q) acc[i][j][q] = 0.f;

        const int gin = sIn[gr];
        const float* frow = (gin >= 0) ? feat + (size_t)gin * fstride : nullptr;

        float4 va[4];
        auto gatherA = [&](int it) {
            const int c0 = it * 32;
#pragma unroll
            for (int i = 0; i < 4; ++i) {
                float4 v = make_float4(0.f, 0.f, 0.f, 0.f);
                if (frow) {
                    v = *reinterpret_cast<const float4*>(frow + c0 + gcb + i * 4);
                    if (RELUIN) {
                        v.x = fmaxf(v.x, 0.f);
                        v.y = fmaxf(v.y, 0.f);
                        v.z = fmaxf(v.z, 0.f);
                        v.w = fmaxf(v.w, 0.f);
                    }
                }
                va[i] = v;
            }
        };
        auto storeA = [&](int stage) {
            char* base_h = dyn + (stage * 2 + 0) * AB;
            char* base_l = dyn + (stage * 2 + 1) * AB;
            const int roff = gr * 80;
#pragma unroll
            for (int i = 0; i < 4; ++i) {
                float4 v = va[i];
                float hx = __bfloat162float(__float2bfloat16(v.x));
                float hy = __bfloat162float(__float2bfloat16(v.y));
                float hz = __bfloat162float(__float2bfloat16(v.z));
                float hw = __bfloat162float(__float2bfloat16(v.w));
                uint2 uh = make_uint2(pkbf(hx, hy), pkbf(hz, hw));
                uint2 ul = make_uint2(pkbf(v.x - hx, v.y - hy),
                                      pkbf(v.z - hz, v.w - hw));
                const int boff = roff + (gcb + i * 4) * 2;
                *reinterpret_cast<uint2*>(base_h + boff) = uh;
                *reinterpret_cast<uint2*>(base_l + boff) = ul;
            }
        };
        auto issueB = [&](int it, int stage) {
            const size_t base = ((size_t)tap * COUTPAD + n0) * CINPAD + it * 32;
#pragma unroll
            for (int q = 0; q < BQ; ++q) {
                const int e = t + q * 256;
                const int plane = e / (NT * 4);
                const int re = e - plane * (NT * 4);
                const int row = re >> 2, seg = re & 3;
                const __nv_bfloat16* src =
                    (plane ? Wlo : Whi) + base + (size_t)row * CINPAD + seg * 8;
                const uint32_t dst =
                    sb + 4 * AB + (uint32_t)(stage * 2 + plane) * BB + row * 80 + seg * 16;
                cpasync16(dst, src);
            }
        };

        gatherA(0);
        issueB(0, 0);
        CP_COMMIT();
        storeA(0);
        CP_WAIT0();
        __syncthreads();

#pragma unroll 1
        for (int it = 0; it < CH; ++it) {
            const int cur = it & 1, nxt = cur ^ 1;
            const bool more = (it + 1 < CH);
            if (more) {
                gatherA(it + 1);
                issueB(it + 1, nxt);
                CP_COMMIT();
            }
            const uint32_t aH = sb + (uint32_t)(cur * 2 + 0) * AB;
            const uint32_t aL = sb + (uint32_t)(cur * 2 + 1) * AB;
            const uint32_t bH = sb + 4 * AB + (uint32_t)(cur * 2 + 0) * BB;
            const uint32_t bL = sb + 4 * AB + (uint32_t)(cur * 2 + 1) * BB;
#pragma unroll
            for (int ks = 0; ks < 2; ++ks) {
                uint32_t Ah[2][4], Al[2][4];
#pragma unroll
                for (int i = 0; i < 2; ++i) {
                    const uint32_t ao =
                        (uint32_t)((wm * 32 + i * 16 + arow) * 80 + ks * 32 + abyt);
                    ldsm4(Ah[i], aH + ao);
                    ldsm4(Al[i], aL + ao);
                }
#pragma unroll
                for (int jp = 0; jp < JP; ++jp) {
                    const uint32_t bo =
                        (uint32_t)((wn * WN + jp * 16 + nloc) * 80 + ks * 32 + bbyt);
                    uint32_t Bh[4], Bl[4];
                    ldsm4(Bh, bH + bo);
                    ldsm4(Bl, bL + bo);
#pragma unroll
                    for (int i = 0; i < 2; ++i) {
                        mma16816(acc[i][2 * jp],     Ah[i], Bh);
                        mma16816(acc[i][2 * jp],     Al[i], Bh);
                        mma16816(acc[i][2 * jp],     Ah[i], Bl);
                        mma16816(acc[i][2 * jp + 1], Ah[i], Bh + 2);
                        mma16816(acc[i][2 * jp + 1], Al[i], Bh + 2);
                        mma16816(acc[i][2 * jp + 1], Ah[i], Bl + 2);
                    }
                }
            }
            if (more) {
                storeA(nxt);
                CP_WAIT0();
            }
            __syncthreads();
        }

        // ---- epilogue: stage acc tile in smem, coalesced v4 reductions ----
#pragma unroll
        for (int j = 0; j < J; ++j) {
            const int col = wn * WN + j * 8 + tg * 2;
#pragma unroll
            for (int i = 0; i < 2; ++i) {
                const int r1 = wm * 32 + i * 16 + g;
                *reinterpret_cast<float2*>(&sAcc[r1 * RSF + col]) =
                    make_float2(acc[i][j][0], acc[i][j][1]);
                *reinterpret_cast<float2*>(&sAcc[(r1 + 8) * RSF + col]) =
                    make_float2(acc[i][j][2], acc[i][j][3]);
            }
        }
        __syncthreads();

        for (int e = t; e < 128 * NQ; e += 256) {
            const int row = e / NQ, q = e - row * NQ;
            const int ro = sOut[row];
            const int col0 = n0 + q * 4;
            if (ro >= 0 && col0 < COUT) {
                float4 v = *reinterpret_cast<const float4*>(&sAcc[row * RSF + q * 4]);
                red4(out + (size_t)ro * ostride + ocol + col0, v);
            }
        }
    }
}

// ---------------------------------------------------------------------------
// Flow conv (K=343, Cin=2, Cout=128): 512 threads, 16 warps x 4 rows,
// double-buffered, per-warp (4-row) tap skipping.
// ---------------------------------------------------------------------------
__global__ void __launch_bounds__(512)
flow_conv(const float* __restrict__ flow, const int* __restrict__ nbr7,
          const float* __restrict__ W, const float* __restrict__ bias,
          float* __restrict__ out, int N)
{
    constexpr int KK = 343, BM = 64;
    __shared__ float sF[2][BM * 2];
    __shared__ float sW[2][256];
    __shared__ unsigned char sV[2][BM];

    const int t = threadIdx.x;
    const int warp = t >> 5, lane = t & 31;
    const int row0 = blockIdx.x * BM;

    float acc[4][4];
#pragma unroll
    for (int i = 0; i < 4; ++i)
#pragma unroll
        for (int j = 0; j < 4; ++j) acc[i][j] = 0.f;

    auto load_stage = [&](int k, int buf) {
        if (t < BM) {
            int r = row0 + t;
            int idx = (r < N) ? nbr7[(size_t)k * N + r] : -1;
            float2 v = make_float2(0.f, 0.f);
            if (idx >= 0) v = *reinterpret_cast<const float2*>(&flow[(size_t)idx * 2]);
            sF[buf][t * 2] = v.x;
            sF[buf][t * 2 + 1] = v.y;
            sV[buf][t] = (idx >= 0);
        }
        if (t < 256) sW[buf][t] = W[(size_t)k * 256 + t];
    };

    load_stage(0, 0);
    for (int k = 0; k < KK; ++k) {
        __syncthreads();
        if (k + 1 < KK) load_stage(k + 1, (k + 1) & 1);
        const int buf = k & 1;
        const bool myv = (lane < 4) && (sV[buf][warp * 4 + lane] != 0);
        if (__ballot_sync(0xffffffffu, myv)) {
            const float4 w0 = *reinterpret_cast<const float4*>(&sW[buf][lane * 4]);
            const float4 w1 = *reinterpret_cast<const float4*>(&sW[buf][128 + lane * 4]);
#pragma unroll
            for (int i = 0; i < 4; ++i) {
                const float f0 = sF[buf][(warp * 4 + i) * 2];
                const float f1 = sF[buf][(warp * 4 + i) * 2 + 1];
                acc[i][0] = fmaf(f0, w0.x, fmaf(f1, w1.x, acc[i][0]));
                acc[i][1] = fmaf(f0, w0.y, fmaf(f1, w1.y, acc[i][1]));
                acc[i][2] = fmaf(f0, w0.z, fmaf(f1, w1.z, acc[i][2]));
                acc[i][3] = fmaf(f0, w0.w, fmaf(f1, w1.w, acc[i][3]));
            }
        }
    }

    const float4 bv = *reinterpret_cast<const float4*>(&bias[lane * 4]);
#pragma unroll
    for (int i = 0; i < 4; ++i) {
        const int r = row0 + warp * 4 + i;
        if (r >= N) continue;
        float4 o;
        o.x = fmaxf(acc[i][0] + bv.x, 0.f);
        o.y = fmaxf(acc[i][1] + bv.y, 0.f);
        o.z = fmaxf(acc[i][2] + bv.z, 0.f);
        o.w = fmaxf(acc[i][3] + bv.w, 0.f);
        *reinterpret_cast<float4*>(out + (size_t)r * 128 + lane * 4) = o;
    }
}

__global__ void tail_copy(const float* __restrict__ ext,
                          const float* __restrict__ flow,
                          float* __restrict__ out, int N)
{
    int i = blockIdx.x * blockDim.x + threadIdx.x;
    if (i >= N * 8) return;
    int r = i >> 3, c = i & 7;
    float v = (c < 2) ? flow[(size_t)r * 2 + c] : ext[(size_t)r * 6 + (c - 2)];
    out[(size_t)r * 128 + 120 + c] = v;
}

// ---------------------------------------------------------------------------
extern "C" void kernel_launch(void* const* d_in, const int* in_sizes, int n_in,
                              void* d_out, int out_size)
{
    const float* extr  = (const float*)d_in[0];
    const float* flow  = (const float*)d_in[1];
    const float* corrf = (const float*)d_in[2];
    const int*   nbr3  = (const int*)  d_in[3];
    const int*   nbr7  = (const int*)  d_in[4];
    const float* Wc1   = (const float*)d_in[5];
    const float* bc1   = (const float*)d_in[6];
    const float* Wc2   = (const float*)d_in[7];
    const float* bc2   = (const float*)d_in[8];
    const float* Wf1   = (const float*)d_in[9];
    const float* bf1   = (const float*)d_in[10];
    const float* Wf2   = (const float*)d_in[11];
    const float* bf2   = (const float*)d_in[12];
    const float* Wcat  = (const float*)d_in[13];
    const float* bcat  = (const float*)d_in[14];
    float* out = (float*)d_out;

    const int N = in_sizes[0] / 6;

    float *p_corr1, *p_f1, *p_cat;
    cudaGetSymbolAddress((void**)&p_corr1, g_corr1);
    cudaGetSymbolAddress((void**)&p_f1,    g_f1);
    cudaGetSymbolAddress((void**)&p_cat,   g_cat);
    __nv_bfloat16 *c1h, *c1l, *c2h, *c2l, *f2h, *f2l, *cth, *ctl;
    cudaGetSymbolAddress((void**)&c1h, gW_c1_hi);
    cudaGetSymbolAddress((void**)&c1l, gW_c1_lo);
    cudaGetSymbolAddress((void**)&c2h, gW_c2_hi);
    cudaGetSymbolAddress((void**)&c2l, gW_c2_lo);
    cudaGetSymbolAddress((void**)&f2h, gW_f2_hi);
    cudaGetSymbolAddress((void**)&f2l, gW_f2_lo);
    cudaGetSymbolAddress((void**)&cth, gW_ct_hi);
    cudaGetSymbolAddress((void**)&ctl, gW_ct_lo);

    int nsm = 148;
    cudaDeviceGetAttribute(&nsm, cudaDevAttrMultiProcessorCount, 0);
    const int pgrid = nsm * 2;

    // ---- weight prep + rulebook build + schedule ----
    prep_w<1, 324, 256, 352, 256><<<(1 * 256 * 352 + 255) / 256, 256>>>(Wc1, c1h, c1l);
    prep_w<27, 256, 192, 256, 192><<<(27 * 192 * 256 + 255) / 256, 256>>>(Wc2, c2h, c2l);
    prep_w<27, 128, 64, 128, 64><<<(27 * 64 * 128 + 255) / 256, 256>>>(Wf2, f2h, f2l);
    prep_w<27, 256, 120, 256, 128><<<(27 * 128 * 256 + 255) / 256, 256>>>(Wcat, cth, ctl);
    zero_cnt<<<1, 32>>>();
    build_list<<<dim3((N + 255) / 256, 27), 256>>>(nbr3, N);
    sched<<<1, 32>>>();

    const int mblk = (N + 127) / 128;
    auto dsm = [](int NT) { return 4 * 10240 + 4 * NT * 80; };

    cudaFuncSetAttribute(tmma<1, 324, 352, 128>,
                         cudaFuncAttributeMaxDynamicSharedMemorySize, dsm(128));
    cudaFuncSetAttribute(tap_mma_p<256, 256, 96, 2, false>,
                         cudaFuncAttributeMaxDynamicSharedMemorySize, dsm(96));
    cudaFuncSetAttribute(tap_mma_p<128, 128, 64, 1, false>,
                         cudaFuncAttributeMaxDynamicSharedMemorySize, dsm(64));
    cudaFuncSetAttribute(tap_mma_p<256, 256, 128, 1, true>,
                         cudaFuncAttributeMaxDynamicSharedMemorySize, dsm(128));

    // corr1 = relu(corrf @ Wc1 + bc1)  (dense identity)
    tmma<1, 324, 352, 128><<<dim3(mblk, 2), 256, dsm(128)>>>(
        corrf, 324, c1h, c1l, 256, bc1, p_corr1, 256, 0, 256, N);

    // f1 = relu(flow_conv)
    flow_conv<<<(N + 63) / 64, 512>>>(flow, nbr7, Wf1, bf1, p_f1, N);

    // cat = bias, then rulebook accumulate (relu fused into consumer)
    init_cat<<<((long)N * 256 + 255) / 256, 256>>>(p_cat, bc2, bf2, N);

    tap_mma_p<256, 256, 96, 2, false><<<pgrid, 256, dsm(96)>>>(
        p_corr1, 256, c2h, c2l, 192, p_cat, 256, 0, 192);
    tap_mma_p<128, 128, 64, 1, false><<<pgrid, 256, dsm(64)>>>(
        p_f1, 128, f2h, f2l, 64, p_cat, 256, 192, 64);

    // out[:,0:120]: bias init, rulebook conv over relu(cat), final relu
    init_bias<<<((long)N * 120 + 255) / 256, 256>>>(out, 128, 0, bcat, 120, N);
    tap_mma_p<256, 256, 128, 1, true><<<pgrid, 256, dsm(128)>>>(
        p_cat, 256, cth, ctl, 128, out, 128, 0, 120);
    relu_region<<<((long)N * 120 + 255) / 256, 256>>>(out, 128, 0, 120, N);

    tail_copy<<<(N * 8 + 255) / 256, 256>>>(extr, flow, out, N);
}